// round 1
// baseline (speedup 1.0000x reference)
#include <cuda_runtime.h>
#include <math.h>
#include <stdint.h>

// ---------------- problem constants ----------------
static constexpr int BATCH  = 8;
static constexpr int DM     = 768;
static constexpr int HEADS  = 12;
static constexpr int LAYERS = 12;
static constexpr int NTOK   = 785;   // 1 + 28*28
static constexpr int NPATCH = 784;
static constexpr int MTOK   = BATCH * NTOK;    // 6280
static constexpr int MPATCH = BATCH * NPATCH;  // 6272
static constexpr int IMG    = 448;
static constexpr int PSZ    = 16;
static constexpr int GRID28 = 28;

// ---------------- scratch (device globals; no allocations allowed) ----------------
__device__ float g_patches[(size_t)MPATCH * DM];                      // im2col
__device__ float g_h[(size_t)MTOK * DM];                              // residual stream
__device__ float g_y[(size_t)MTOK * DM];                              // LN out / attn out
__device__ float g_qkv[(size_t)MTOK * 3 * DM];                        // qkv
__device__ float g_mid[(size_t)MTOK * 4 * DM];                        // mlp hidden
__device__ float g_scores[(size_t)BATCH * HEADS * NTOK * NTOK];       // attn scores

// ---------------- reductions ----------------
__device__ __forceinline__ float warpSum(float v) {
#pragma unroll
    for (int o = 16; o > 0; o >>= 1) v += __shfl_xor_sync(0xffffffffu, v, o);
    return v;
}
__device__ __forceinline__ float warpMax(float v) {
#pragma unroll
    for (int o = 16; o > 0; o >>= 1) v = fmaxf(v, __shfl_xor_sync(0xffffffffu, v, o));
    return v;
}
// 256-thread block reductions; shared buffer of 8 floats, safe for repeated use.
__device__ __forceinline__ float blockSum256(float v, float* sh) {
    int lane = threadIdx.x & 31, w = threadIdx.x >> 5;
    v = warpSum(v);
    if (lane == 0) sh[w] = v;
    __syncthreads();
    float r = (threadIdx.x < 8) ? sh[threadIdx.x] : 0.f;
    if (w == 0) {
        r = warpSum(r);
        if (lane == 0) sh[0] = r;
    }
    __syncthreads();
    r = sh[0];
    __syncthreads();
    return r;
}
__device__ __forceinline__ float blockMax256(float v, float* sh) {
    int lane = threadIdx.x & 31, w = threadIdx.x >> 5;
    v = warpMax(v);
    if (lane == 0) sh[w] = v;
    __syncthreads();
    float r = (threadIdx.x < 8) ? sh[threadIdx.x] : -1e30f;
    if (w == 0) {
        r = warpMax(r);
        if (lane == 0) sh[0] = r;
    }
    __syncthreads();
    r = sh[0];
    __syncthreads();
    return r;
}

// ---------------- im2col: x[B,3,448,448] -> patches[6272, 768] (k = c*256 + i*16 + j) ----------------
__global__ void im2col_kernel(const float* __restrict__ x, float* __restrict__ P) {
    int idx = blockIdx.x * blockDim.x + threadIdx.x;
    if (idx >= MPATCH * DM) return;
    int k = idx % DM, m = idx / DM;
    int b = m / NPATCH, t = m % NPATCH;
    int py = t / GRID28, px = t % GRID28;
    int c = k >> 8, rem = k & 255, i = rem >> 4, j = rem & 15;
    size_t src = (((size_t)(b * 3 + c) * IMG) + (size_t)(py * PSZ + i)) * IMG + (px * PSZ + j);
    P[idx] = x[src];
}

// ---------------- assemble: h[b,0]=cls+pos[0]; h[b,1+t]=tok[b,t]+pos[1+t] ----------------
__global__ void assemble_kernel(const float* __restrict__ tok, const float* __restrict__ cls,
                                const float* __restrict__ pos, float* __restrict__ H) {
    int idx = blockIdx.x * blockDim.x + threadIdx.x;
    if (idx >= MTOK * DM) return;
    int d = idx % DM;
    int r = idx / DM;
    int n = r % NTOK, b = r / NTOK;
    float v;
    if (n == 0) v = cls[d] + pos[d];
    else        v = tok[((size_t)b * NPATCH + (n - 1)) * DM + d] + pos[(size_t)n * DM + d];
    H[idx] = v;
}

// ---------------- LayerNorm over D=768 (256 threads, 3 elems/thread) ----------------
__global__ void ln_kernel(const float* __restrict__ X, const float* __restrict__ g,
                          const float* __restrict__ bb, float* __restrict__ Y,
                          long long inStride, long long outStride) {
    const float* x = X + (long long)blockIdx.x * inStride;
    float* y = Y + (long long)blockIdx.x * outStride;
    int t = threadIdx.x;
    __shared__ float sh[8];
    float v0 = x[t], v1 = x[t + 256], v2 = x[t + 512];
    float mu = blockSum256(v0 + v1 + v2, sh) * (1.0f / 768.0f);
    float d0 = v0 - mu, d1 = v1 - mu, d2 = v2 - mu;
    float var = blockSum256(d0 * d0 + d1 * d1 + d2 * d2, sh) * (1.0f / 768.0f);
    float rs = rsqrtf(var + 1e-5f);
    y[t]       = d0 * rs * g[t]       + bb[t];
    y[t + 256] = d1 * rs * g[t + 256] + bb[t + 256];
    y[t + 512] = d2 * rs * g[t + 512] + bb[t + 512];
}

// ---------------- softmax over 785 cols, in-place (256 threads) ----------------
__global__ void softmax_kernel(float* __restrict__ S) {
    float* row = S + (size_t)blockIdx.x * NTOK;
    int t = threadIdx.x;
    __shared__ float sh[8];
    float v0 = row[t], v1 = row[t + 256], v2 = row[t + 512];
    float v3 = (t < NTOK - 768) ? row[t + 768] : -1e30f;
    float mx = blockMax256(fmaxf(fmaxf(v0, v1), fmaxf(v2, v3)), sh);
    float e0 = expf(v0 - mx), e1 = expf(v1 - mx), e2 = expf(v2 - mx);
    float e3 = (t < NTOK - 768) ? expf(v3 - mx) : 0.f;
    float s = blockSum256(e0 + e1 + e2 + e3, sh);
    float inv = 1.0f / s;
    row[t] = e0 * inv; row[t + 256] = e1 * inv; row[t + 512] = e2 * inv;
    if (t < NTOK - 768) row[t + 768] = e3 * inv;
}

// ---------------- generic tiled fp32 GEMM ----------------
// C[m,n] = alpha * sum_k A[m,k] * (TRANSB ? B[n,k] : B[k,n])   (+ epilogue)
// EPI: 0 none, 1 +bias[n], 2 +bias[n]+Res[m,n], 3 gelu(x+bias[n])
// batched: z = blockIdx.z, zo=z/zdiv, zi=z%zdiv; ptr += zo*s?o + zi*s?i
template <int BM, int BN, int BK, int TM, int TN, bool TRANSB, int EPI>
__global__ void __launch_bounds__((BM / TM) * (BN / TN), 2)
gemm_kernel(const float* __restrict__ Ag, const float* __restrict__ Bg,
            float* __restrict__ Cg, const float* __restrict__ bias,
            const float* __restrict__ Res,
            int M, int N, int K, int lda, int ldb, int ldc,
            int zdiv, long long sAo, long long sAi, long long sBo, long long sBi,
            long long sCo, long long sCi, float alpha) {
    constexpr int THREADS = (BM / TM) * (BN / TN);
    constexpr int AL = BM * BK / THREADS;
    constexpr int BL = BK * BN / THREADS;
    __shared__ float As[BK][BM + 4];
    __shared__ float Bs[BK][BN + 4];

    int z = blockIdx.z;
    int zo = z / zdiv, zi = z % zdiv;
    Ag += zo * sAo + zi * sAi;
    Bg += zo * sBo + zi * sBi;
    Cg += zo * sCo + zi * sCi;
    if (Res) Res += zo * sCo + zi * sCi;

    const int row0 = blockIdx.y * BM, col0 = blockIdx.x * BN;
    const int tid = threadIdx.x;
    const int tm0 = (tid / (BN / TN)) * TM;
    const int tn0 = (tid % (BN / TN)) * TN;

    float acc[TM][TN];
#pragma unroll
    for (int i = 0; i < TM; i++)
#pragma unroll
        for (int j = 0; j < TN; j++) acc[i][j] = 0.f;

    float ra[AL], rb[BL];

    auto ldgA = [&](int kt) {
#pragma unroll
        for (int i = 0; i < AL; i++) {
            int idx = tid + i * THREADS;
            int m = idx / BK, k = idx % BK;
            int gm = row0 + m, gk = kt + k;
            ra[i] = (gm < M && gk < K) ? __ldg(&Ag[(size_t)gm * lda + gk]) : 0.f;
        }
    };
    auto ldgB = [&](int kt) {
#pragma unroll
        for (int i = 0; i < BL; i++) {
            int idx = tid + i * THREADS;
            if (TRANSB) {
                int n = idx / BK, k = idx % BK;
                int gn = col0 + n, gk = kt + k;
                rb[i] = (gn < N && gk < K) ? __ldg(&Bg[(size_t)gn * ldb + gk]) : 0.f;
            } else {
                int k = idx / BN, n = idx % BN;
                int gn = col0 + n, gk = kt + k;
                rb[i] = (gk < K && gn < N) ? __ldg(&Bg[(size_t)gk * ldb + gn]) : 0.f;
            }
        }
    };
    auto stsAB = [&]() {
#pragma unroll
        for (int i = 0; i < AL; i++) {
            int idx = tid + i * THREADS;
            int m = idx / BK, k = idx % BK;
            As[k][m] = ra[i];
        }
#pragma unroll
        for (int i = 0; i < BL; i++) {
            int idx = tid + i * THREADS;
            if (TRANSB) {
                int n = idx / BK, k = idx % BK;
                Bs[k][n] = rb[i];
            } else {
                int k = idx / BN, n = idx % BN;
                Bs[k][n] = rb[i];
            }
        }
    };
    auto compute = [&]() {
#pragma unroll
        for (int k = 0; k < BK; k++) {
            float a[TM], b[TN];
#pragma unroll
            for (int i = 0; i < TM; i += 4) {
                float4 t4 = *reinterpret_cast<const float4*>(&As[k][tm0 + i]);
                a[i] = t4.x; a[i + 1] = t4.y; a[i + 2] = t4.z; a[i + 3] = t4.w;
            }
#pragma unroll
            for (int j = 0; j < TN; j += 4) {
                float4 t4 = *reinterpret_cast<const float4*>(&Bs[k][tn0 + j]);
                b[j] = t4.x; b[j + 1] = t4.y; b[j + 2] = t4.z; b[j + 3] = t4.w;
            }
#pragma unroll
            for (int i = 0; i < TM; i++)
#pragma unroll
                for (int j = 0; j < TN; j++) acc[i][j] = fmaf(a[i], b[j], acc[i][j]);
        }
    };

    ldgA(0); ldgB(0);
    stsAB();
    __syncthreads();
    for (int kt = BK; kt < K; kt += BK) {
        ldgA(kt); ldgB(kt);
        compute();
        __syncthreads();
        stsAB();
        __syncthreads();
    }
    compute();

#pragma unroll
    for (int i = 0; i < TM; i++) {
        int gm = row0 + tm0 + i;
        if (gm >= M) continue;
#pragma unroll
        for (int j = 0; j < TN; j++) {
            int gn = col0 + tn0 + j;
            if (gn >= N) continue;
            float v = acc[i][j] * alpha;
            if (EPI >= 1) v += bias[gn];
            if (EPI == 2) v += Res[(size_t)gm * ldc + gn];
            if (EPI == 3) v = 0.5f * v * (1.0f + erff(v * 0.70710678118654752f));
            Cg[(size_t)gm * ldc + gn] = v;
        }
    }
}

// ---------------- host launchers ----------------
template <int BM, int BN, bool TRANSB, int EPI>
static void launch_gemm(const float* A, const float* B, float* C,
                        const float* bias, const float* res,
                        int M, int N, int K, int lda, int ldb, int ldc,
                        int Z, int zdiv,
                        long long sAo, long long sAi, long long sBo, long long sBi,
                        long long sCo, long long sCi, float alpha) {
    constexpr int BK = 16, TM = 8, TN = 8;
    constexpr int THREADS = (BM / TM) * (BN / TN);
    dim3 grid((N + BN - 1) / BN, (M + BM - 1) / BM, Z);
    gemm_kernel<BM, BN, BK, TM, TN, TRANSB, EPI><<<grid, THREADS>>>(
        A, B, C, bias, res, M, N, K, lda, ldb, ldc, zdiv,
        sAo, sAi, sBo, sBi, sCo, sCi, alpha);
}

extern "C" void kernel_launch(void* const* d_in, const int* in_sizes, int n_in,
                              void* d_out, int out_size) {
    const float* x       = (const float*)d_in[0];
    const float* conv_w  = (const float*)d_in[1];
    const float* conv_b  = (const float*)d_in[2];
    const float* cls_tok = (const float*)d_in[3];
    const float* pos_emb = (const float*)d_in[4];
    const float* ln1_g   = (const float*)d_in[5];
    const float* ln1_b   = (const float*)d_in[6];
    const float* qkv_w   = (const float*)d_in[7];
    const float* qkv_b   = (const float*)d_in[8];
    const float* proj_w  = (const float*)d_in[9];
    const float* proj_b  = (const float*)d_in[10];
    const float* ln2_g   = (const float*)d_in[11];
    const float* ln2_b   = (const float*)d_in[12];
    const float* mlp_w1  = (const float*)d_in[13];
    const float* mlp_b1  = (const float*)d_in[14];
    const float* mlp_w2  = (const float*)d_in[15];
    const float* mlp_b2  = (const float*)d_in[16];
    const float* lnf_g   = (const float*)d_in[17];
    const float* lnf_b   = (const float*)d_in[18];
    float* out = (float*)d_out;

    float *ppatch, *ph, *py, *pqkv, *pmid, *pscores;
    cudaGetSymbolAddress((void**)&ppatch, g_patches);
    cudaGetSymbolAddress((void**)&ph, g_h);
    cudaGetSymbolAddress((void**)&py, g_y);
    cudaGetSymbolAddress((void**)&pqkv, g_qkv);
    cudaGetSymbolAddress((void**)&pmid, g_mid);
    cudaGetSymbolAddress((void**)&pscores, g_scores);

    const long long ZS = 0;

    // 1) patch embed: im2col -> GEMM (B = conv_w [768out, 768k], NT) + bias
    im2col_kernel<<<(MPATCH * DM + 255) / 256, 256>>>(x, ppatch);
    launch_gemm<128, 128, true, 1>(ppatch, conv_w, py, conv_b, nullptr,
                                   MPATCH, DM, DM, DM, DM, DM,
                                   1, 1, ZS, ZS, ZS, ZS, ZS, ZS, 1.0f);
    // 2) cls + pos (bicubic resize is identity at 28x28)
    assemble_kernel<<<(MTOK * DM + 255) / 256, 256>>>(py, cls_tok, pos_emb, ph);

    const float attn_scale = 0.125f;  // (768/12)^-0.5
    for (int l = 0; l < LAYERS; l++) {
        const float* l1g = ln1_g + (size_t)l * DM;
        const float* l1b = ln1_b + (size_t)l * DM;
        const float* qw  = qkv_w + (size_t)l * DM * 3 * DM;
        const float* qb  = qkv_b + (size_t)l * 3 * DM;
        const float* pw  = proj_w + (size_t)l * DM * DM;
        const float* pb  = proj_b + (size_t)l * DM;
        const float* l2g = ln2_g + (size_t)l * DM;
        const float* l2b = ln2_b + (size_t)l * DM;
        const float* w1  = mlp_w1 + (size_t)l * DM * 4 * DM;
        const float* b1  = mlp_b1 + (size_t)l * 4 * DM;
        const float* w2  = mlp_w2 + (size_t)l * 4 * DM * DM;
        const float* b2  = mlp_b2 + (size_t)l * DM;

        // LN1
        ln_kernel<<<MTOK, 256>>>(ph, l1g, l1b, py, DM, DM);
        // QKV: [6280,768] @ [768,2304] + bias
        launch_gemm<128, 128, false, 1>(py, qw, pqkv, qb, nullptr,
                                        MTOK, 3 * DM, DM, DM, 3 * DM, 3 * DM,
                                        1, 1, ZS, ZS, ZS, ZS, ZS, ZS, 1.0f);
        // scores[b,h] = Q @ K^T * scale   (96 batches, NT, K=64)
        launch_gemm<128, 128, true, 0>(
            pqkv, pqkv + DM, pscores, nullptr, nullptr,
            NTOK, NTOK, 64, 3 * DM, 3 * DM, NTOK,
            BATCH * HEADS, HEADS,
            (long long)NTOK * 3 * DM, 64,
            (long long)NTOK * 3 * DM, 64,
            (long long)HEADS * NTOK * NTOK, (long long)NTOK * NTOK, attn_scale);
        // softmax rows
        softmax_kernel<<<BATCH * HEADS * NTOK, 256>>>(pscores);
        // attn_out[b,h] = S @ V  -> py at col h*64 (i.e. [B,N,H,dh] layout)
        launch_gemm<128, 64, false, 0>(
            pscores, pqkv + 2 * DM, py, nullptr, nullptr,
            NTOK, 64, NTOK, NTOK, 3 * DM, DM,
            BATCH * HEADS, HEADS,
            (long long)HEADS * NTOK * NTOK, (long long)NTOK * NTOK,
            (long long)NTOK * 3 * DM, 64,
            (long long)NTOK * DM, 64, 1.0f);
        // proj + residual into h
        launch_gemm<128, 128, false, 2>(py, pw, ph, pb, ph,
                                        MTOK, DM, DM, DM, DM, DM,
                                        1, 1, ZS, ZS, ZS, ZS, ZS, ZS, 1.0f);
        // LN2
        ln_kernel<<<MTOK, 256>>>(ph, l2g, l2b, py, DM, DM);
        // MLP1 + exact GELU
        launch_gemm<128, 128, false, 3>(py, w1, pmid, b1, nullptr,
                                        MTOK, 4 * DM, DM, DM, 4 * DM, 4 * DM,
                                        1, 1, ZS, ZS, ZS, ZS, ZS, ZS, 1.0f);
        // MLP2 + residual into h
        launch_gemm<128, 128, false, 2>(pmid, w2, ph, b2, ph,
                                        MTOK, DM, 4 * DM, 4 * DM, DM, DM,
                                        1, 1, ZS, ZS, ZS, ZS, ZS, ZS, 1.0f);
    }

    // final LN of CLS token only (row b*785), out [8,768]
    ln_kernel<<<BATCH, 256>>>(ph, lnf_g, lnf_b, out, (long long)NTOK * DM, DM);
}

// round 2
// speedup vs baseline: 1.0003x; 1.0003x over previous
#include <cuda_runtime.h>
#include <math.h>
#include <stdint.h>

// ---------------- problem constants ----------------
static constexpr int BATCH  = 8;
static constexpr int DM     = 768;
static constexpr int HEADS  = 12;
static constexpr int LAYERS = 12;
static constexpr int NTOK   = 785;   // 1 + 28*28
static constexpr int NPATCH = 784;
static constexpr int MTOK   = BATCH * NTOK;    // 6280
static constexpr int MPATCH = BATCH * NPATCH;  // 6272
static constexpr int IMG    = 448;
static constexpr int PSZ    = 16;
static constexpr int GRID28 = 28;

// ---------------- scratch (device globals; no allocations allowed) ----------------
__device__ float g_patches[(size_t)MPATCH * DM];                      // im2col
__device__ float g_h[(size_t)MTOK * DM];                              // residual stream
__device__ float g_y[(size_t)MTOK * DM];                              // LN out / attn out
__device__ float g_qkv[(size_t)MTOK * 3 * DM];                        // qkv
__device__ float g_mid[(size_t)MTOK * 4 * DM];                        // mlp hidden
__device__ float g_scores[(size_t)BATCH * HEADS * NTOK * NTOK];       // attn scores

// ---------------- reductions ----------------
__device__ __forceinline__ float warpSum(float v) {
#pragma unroll
    for (int o = 16; o > 0; o >>= 1) v += __shfl_xor_sync(0xffffffffu, v, o);
    return v;
}
__device__ __forceinline__ float warpMax(float v) {
#pragma unroll
    for (int o = 16; o > 0; o >>= 1) v = fmaxf(v, __shfl_xor_sync(0xffffffffu, v, o));
    return v;
}
// 256-thread block reductions; shared buffer of 8 floats, safe for repeated use.
__device__ __forceinline__ float blockSum256(float v, float* sh) {
    int lane = threadIdx.x & 31, w = threadIdx.x >> 5;
    v = warpSum(v);
    if (lane == 0) sh[w] = v;
    __syncthreads();
    float r = (threadIdx.x < 8) ? sh[threadIdx.x] : 0.f;
    if (w == 0) {
        r = warpSum(r);
        if (lane == 0) sh[0] = r;
    }
    __syncthreads();
    r = sh[0];
    __syncthreads();
    return r;
}
__device__ __forceinline__ float blockMax256(float v, float* sh) {
    int lane = threadIdx.x & 31, w = threadIdx.x >> 5;
    v = warpMax(v);
    if (lane == 0) sh[w] = v;
    __syncthreads();
    float r = (threadIdx.x < 8) ? sh[threadIdx.x] : -1e30f;
    if (w == 0) {
        r = warpMax(r);
        if (lane == 0) sh[0] = r;
    }
    __syncthreads();
    r = sh[0];
    __syncthreads();
    return r;
}

// ---------------- im2col: x[B,3,448,448] -> patches[6272, 768] (k = c*256 + i*16 + j) ----------------
__global__ void im2col_kernel(const float* __restrict__ x, float* __restrict__ P) {
    int idx = blockIdx.x * blockDim.x + threadIdx.x;
    if (idx >= MPATCH * DM) return;
    int k = idx % DM, m = idx / DM;
    int b = m / NPATCH, t = m % NPATCH;
    int py = t / GRID28, px = t % GRID28;
    int c = k >> 8, rem = k & 255, i = rem >> 4, j = rem & 15;
    size_t src = (((size_t)(b * 3 + c) * IMG) + (size_t)(py * PSZ + i)) * IMG + (px * PSZ + j);
    P[idx] = x[src];
}

// ---------------- assemble: h[b,0]=cls+pos[0]; h[b,1+t]=tok[b,t]+pos[1+t] ----------------
__global__ void assemble_kernel(const float* __restrict__ tok, const float* __restrict__ cls,
                                const float* __restrict__ pos, float* __restrict__ H) {
    int idx = blockIdx.x * blockDim.x + threadIdx.x;
    if (idx >= MTOK * DM) return;
    int d = idx % DM;
    int r = idx / DM;
    int n = r % NTOK, b = r / NTOK;
    float v;
    if (n == 0) v = cls[d] + pos[d];
    else        v = tok[((size_t)b * NPATCH + (n - 1)) * DM + d] + pos[(size_t)n * DM + d];
    H[idx] = v;
}

// ---------------- LayerNorm over D=768 (256 threads, 3 elems/thread) ----------------
__global__ void ln_kernel(const float* __restrict__ X, const float* __restrict__ g,
                          const float* __restrict__ bb, float* __restrict__ Y,
                          long long inStride, long long outStride) {
    const float* x = X + (long long)blockIdx.x * inStride;
    float* y = Y + (long long)blockIdx.x * outStride;
    int t = threadIdx.x;
    __shared__ float sh[8];
    float v0 = x[t], v1 = x[t + 256], v2 = x[t + 512];
    float mu = blockSum256(v0 + v1 + v2, sh) * (1.0f / 768.0f);
    float d0 = v0 - mu, d1 = v1 - mu, d2 = v2 - mu;
    float var = blockSum256(d0 * d0 + d1 * d1 + d2 * d2, sh) * (1.0f / 768.0f);
    float rs = rsqrtf(var + 1e-5f);
    y[t]       = d0 * rs * g[t]       + bb[t];
    y[t + 256] = d1 * rs * g[t + 256] + bb[t + 256];
    y[t + 512] = d2 * rs * g[t + 512] + bb[t + 512];
}

// ---------------- softmax over 785 cols, in-place (256 threads) ----------------
__global__ void softmax_kernel(float* __restrict__ S) {
    float* row = S + (size_t)blockIdx.x * NTOK;
    int t = threadIdx.x;
    __shared__ float sh[8];
    float v0 = row[t], v1 = row[t + 256], v2 = row[t + 512];
    float v3 = (t < NTOK - 768) ? row[t + 768] : -1e30f;
    float mx = blockMax256(fmaxf(fmaxf(v0, v1), fmaxf(v2, v3)), sh);
    float e0 = expf(v0 - mx), e1 = expf(v1 - mx), e2 = expf(v2 - mx);
    float e3 = (t < NTOK - 768) ? expf(v3 - mx) : 0.f;
    float s = blockSum256(e0 + e1 + e2 + e3, sh);
    float inv = 1.0f / s;
    row[t] = e0 * inv; row[t + 256] = e1 * inv; row[t + 512] = e2 * inv;
    if (t < NTOK - 768) row[t + 768] = e3 * inv;
}

// ---------------- generic tiled fp32 GEMM ----------------
// C[m,n] = alpha * sum_k A[m,k] * (TRANSB ? B[n,k] : B[k,n])   (+ epilogue)
// EPI: 0 none, 1 +bias[n], 2 +bias[n]+Res[m,n], 3 gelu(x+bias[n])
// batched: z = blockIdx.z, zo=z/zdiv, zi=z%zdiv; ptr += zo*s?o + zi*s?i
template <int BM, int BN, int BK, int TM, int TN, bool TRANSB, int EPI>
__global__ void __launch_bounds__((BM / TM) * (BN / TN), 2)
gemm_kernel(const float* __restrict__ Ag, const float* __restrict__ Bg,
            float* __restrict__ Cg, const float* __restrict__ bias,
            const float* __restrict__ Res,
            int M, int N, int K, int lda, int ldb, int ldc,
            int zdiv, long long sAo, long long sAi, long long sBo, long long sBi,
            long long sCo, long long sCi, float alpha) {
    constexpr int THREADS = (BM / TM) * (BN / TN);
    constexpr int AL = BM * BK / THREADS;
    constexpr int BL = BK * BN / THREADS;
    __shared__ float As[BK][BM + 4];
    __shared__ float Bs[BK][BN + 4];

    int z = blockIdx.z;
    int zo = z / zdiv, zi = z % zdiv;
    Ag += zo * sAo + zi * sAi;
    Bg += zo * sBo + zi * sBi;
    Cg += zo * sCo + zi * sCi;
    if (Res) Res += zo * sCo + zi * sCi;

    const int row0 = blockIdx.y * BM, col0 = blockIdx.x * BN;
    const int tid = threadIdx.x;
    const int tm0 = (tid / (BN / TN)) * TM;
    const int tn0 = (tid % (BN / TN)) * TN;

    float acc[TM][TN];
#pragma unroll
    for (int i = 0; i < TM; i++)
#pragma unroll
        for (int j = 0; j < TN; j++) acc[i][j] = 0.f;

    float ra[AL], rb[BL];

    auto ldgA = [&](int kt) {
#pragma unroll
        for (int i = 0; i < AL; i++) {
            int idx = tid + i * THREADS;
            int m = idx / BK, k = idx % BK;
            int gm = row0 + m, gk = kt + k;
            ra[i] = (gm < M && gk < K) ? __ldg(&Ag[(size_t)gm * lda + gk]) : 0.f;
        }
    };
    auto ldgB = [&](int kt) {
#pragma unroll
        for (int i = 0; i < BL; i++) {
            int idx = tid + i * THREADS;
            if (TRANSB) {
                int n = idx / BK, k = idx % BK;
                int gn = col0 + n, gk = kt + k;
                rb[i] = (gn < N && gk < K) ? __ldg(&Bg[(size_t)gn * ldb + gk]) : 0.f;
            } else {
                int k = idx / BN, n = idx % BN;
                int gn = col0 + n, gk = kt + k;
                rb[i] = (gk < K && gn < N) ? __ldg(&Bg[(size_t)gk * ldb + gn]) : 0.f;
            }
        }
    };
    auto stsAB = [&]() {
#pragma unroll
        for (int i = 0; i < AL; i++) {
            int idx = tid + i * THREADS;
            int m = idx / BK, k = idx % BK;
            As[k][m] = ra[i];
        }
#pragma unroll
        for (int i = 0; i < BL; i++) {
            int idx = tid + i * THREADS;
            if (TRANSB) {
                int n = idx / BK, k = idx % BK;
                Bs[k][n] = rb[i];
            } else {
                int k = idx / BN, n = idx % BN;
                Bs[k][n] = rb[i];
            }
        }
    };
    auto compute = [&]() {
#pragma unroll
        for (int k = 0; k < BK; k++) {
            float a[TM], b[TN];
#pragma unroll
            for (int i = 0; i < TM; i += 4) {
                float4 t4 = *reinterpret_cast<const float4*>(&As[k][tm0 + i]);
                a[i] = t4.x; a[i + 1] = t4.y; a[i + 2] = t4.z; a[i + 3] = t4.w;
            }
#pragma unroll
            for (int j = 0; j < TN; j += 4) {
                float4 t4 = *reinterpret_cast<const float4*>(&Bs[k][tn0 + j]);
                b[j] = t4.x; b[j + 1] = t4.y; b[j + 2] = t4.z; b[j + 3] = t4.w;
            }
#pragma unroll
            for (int i = 0; i < TM; i++)
#pragma unroll
                for (int j = 0; j < TN; j++) acc[i][j] = fmaf(a[i], b[j], acc[i][j]);
        }
    };

    ldgA(0); ldgB(0);
    stsAB();
    __syncthreads();
    for (int kt = BK; kt < K; kt += BK) {
        ldgA(kt); ldgB(kt);
        compute();
        __syncthreads();
        stsAB();
        __syncthreads();
    }
    compute();

#pragma unroll
    for (int i = 0; i < TM; i++) {
        int gm = row0 + tm0 + i;
        if (gm >= M) continue;
#pragma unroll
        for (int j = 0; j < TN; j++) {
            int gn = col0 + tn0 + j;
            if (gn >= N) continue;
            float v = acc[i][j] * alpha;
            if (EPI >= 1) v += bias[gn];
            if (EPI == 2) v += Res[(size_t)gm * ldc + gn];
            if (EPI == 3) v = 0.5f * v * (1.0f + erff(v * 0.70710678118654752f));
            Cg[(size_t)gm * ldc + gn] = v;
        }
    }
}

// ---------------- host launchers ----------------
template <int BM, int BN, bool TRANSB, int EPI>
static void launch_gemm(const float* A, const float* B, float* C,
                        const float* bias, const float* res,
                        int M, int N, int K, int lda, int ldb, int ldc,
                        int Z, int zdiv,
                        long long sAo, long long sAi, long long sBo, long long sBi,
                        long long sCo, long long sCi, float alpha) {
    constexpr int BK = 16, TM = 8, TN = 8;
    constexpr int THREADS = (BM / TM) * (BN / TN);
    dim3 grid((N + BN - 1) / BN, (M + BM - 1) / BM, Z);
    gemm_kernel<BM, BN, BK, TM, TN, TRANSB, EPI><<<grid, THREADS>>>(
        A, B, C, bias, res, M, N, K, lda, ldb, ldc, zdiv,
        sAo, sAi, sBo, sBi, sCo, sCi, alpha);
}

extern "C" void kernel_launch(void* const* d_in, const int* in_sizes, int n_in,
                              void* d_out, int out_size) {
    const float* x       = (const float*)d_in[0];
    const float* conv_w  = (const float*)d_in[1];
    const float* conv_b  = (const float*)d_in[2];
    const float* cls_tok = (const float*)d_in[3];
    const float* pos_emb = (const float*)d_in[4];
    const float* ln1_g   = (const float*)d_in[5];
    const float* ln1_b   = (const float*)d_in[6];
    const float* qkv_w   = (const float*)d_in[7];
    const float* qkv_b   = (const float*)d_in[8];
    const float* proj_w  = (const float*)d_in[9];
    const float* proj_b  = (const float*)d_in[10];
    const float* ln2_g   = (const float*)d_in[11];
    const float* ln2_b   = (const float*)d_in[12];
    const float* mlp_w1  = (const float*)d_in[13];
    const float* mlp_b1  = (const float*)d_in[14];
    const float* mlp_w2  = (const float*)d_in[15];
    const float* mlp_b2  = (const float*)d_in[16];
    const float* lnf_g   = (const float*)d_in[17];
    const float* lnf_b   = (const float*)d_in[18];
    float* out = (float*)d_out;

    float *ppatch, *ph, *py, *pqkv, *pmid, *pscores;
    cudaGetSymbolAddress((void**)&ppatch, g_patches);
    cudaGetSymbolAddress((void**)&ph, g_h);
    cudaGetSymbolAddress((void**)&py, g_y);
    cudaGetSymbolAddress((void**)&pqkv, g_qkv);
    cudaGetSymbolAddress((void**)&pmid, g_mid);
    cudaGetSymbolAddress((void**)&pscores, g_scores);

    const long long ZS = 0;

    // 1) patch embed: im2col -> GEMM (B = conv_w [768out, 768k], NT) + bias
    im2col_kernel<<<(MPATCH * DM + 255) / 256, 256>>>(x, ppatch);
    launch_gemm<128, 128, true, 1>(ppatch, conv_w, py, conv_b, nullptr,
                                   MPATCH, DM, DM, DM, DM, DM,
                                   1, 1, ZS, ZS, ZS, ZS, ZS, ZS, 1.0f);
    // 2) cls + pos (bicubic resize is identity at 28x28)
    assemble_kernel<<<(MTOK * DM + 255) / 256, 256>>>(py, cls_tok, pos_emb, ph);

    const float attn_scale = 0.125f;  // (768/12)^-0.5
    for (int l = 0; l < LAYERS; l++) {
        const float* l1g = ln1_g + (size_t)l * DM;
        const float* l1b = ln1_b + (size_t)l * DM;
        const float* qw  = qkv_w + (size_t)l * DM * 3 * DM;
        const float* qb  = qkv_b + (size_t)l * 3 * DM;
        const float* pw  = proj_w + (size_t)l * DM * DM;
        const float* pb  = proj_b + (size_t)l * DM;
        const float* l2g = ln2_g + (size_t)l * DM;
        const float* l2b = ln2_b + (size_t)l * DM;
        const float* w1  = mlp_w1 + (size_t)l * DM * 4 * DM;
        const float* b1  = mlp_b1 + (size_t)l * 4 * DM;
        const float* w2  = mlp_w2 + (size_t)l * 4 * DM * DM;
        const float* b2  = mlp_b2 + (size_t)l * DM;

        // LN1
        ln_kernel<<<MTOK, 256>>>(ph, l1g, l1b, py, DM, DM);
        // QKV: [6280,768] @ [768,2304] + bias
        launch_gemm<128, 128, false, 1>(py, qw, pqkv, qb, nullptr,
                                        MTOK, 3 * DM, DM, DM, 3 * DM, 3 * DM,
                                        1, 1, ZS, ZS, ZS, ZS, ZS, ZS, 1.0f);
        // scores[b,h] = Q @ K^T * scale   (96 batches, NT, K=64)
        launch_gemm<128, 128, true, 0>(
            pqkv, pqkv + DM, pscores, nullptr, nullptr,
            NTOK, NTOK, 64, 3 * DM, 3 * DM, NTOK,
            BATCH * HEADS, HEADS,
            (long long)NTOK * 3 * DM, 64,
            (long long)NTOK * 3 * DM, 64,
            (long long)HEADS * NTOK * NTOK, (long long)NTOK * NTOK, attn_scale);
        // softmax rows
        softmax_kernel<<<BATCH * HEADS * NTOK, 256>>>(pscores);
        // attn_out[b,h] = S @ V  -> py at col h*64 (i.e. [B,N,H,dh] layout)
        launch_gemm<128, 64, false, 0>(
            pscores, pqkv + 2 * DM, py, nullptr, nullptr,
            NTOK, 64, NTOK, NTOK, 3 * DM, DM,
            BATCH * HEADS, HEADS,
            (long long)HEADS * NTOK * NTOK, (long long)NTOK * NTOK,
            (long long)NTOK * 3 * DM, 64,
            (long long)NTOK * DM, 64, 1.0f);
        // proj + residual into h
        launch_gemm<128, 128, false, 2>(py, pw, ph, pb, ph,
                                        MTOK, DM, DM, DM, DM, DM,
                                        1, 1, ZS, ZS, ZS, ZS, ZS, ZS, 1.0f);
        // LN2
        ln_kernel<<<MTOK, 256>>>(ph, l2g, l2b, py, DM, DM);
        // MLP1 + exact GELU
        launch_gemm<128, 128, false, 3>(py, w1, pmid, b1, nullptr,
                                        MTOK, 4 * DM, DM, DM, 4 * DM, 4 * DM,
                                        1, 1, ZS, ZS, ZS, ZS, ZS, ZS, 1.0f);
        // MLP2 + residual into h
        launch_gemm<128, 128, false, 2>(pmid, w2, ph, b2, ph,
                                        MTOK, DM, 4 * DM, 4 * DM, DM, DM,
                                        1, 1, ZS, ZS, ZS, ZS, ZS, ZS, 1.0f);
    }

    // final LN of CLS token only (row b*785), out [8,768]
    ln_kernel<<<BATCH, 256>>>(ph, lnf_g, lnf_b, out, (long long)NTOK * DM, DM);
}

// round 4
// speedup vs baseline: 2.1940x; 2.1934x over previous
#include <cuda_runtime.h>
#include <cuda_bf16.h>
#include <math.h>
#include <stdint.h>

using bf16 = __nv_bfloat16;

// ---------------- problem constants ----------------
static constexpr int BATCH  = 8;
static constexpr int DM     = 768;
static constexpr int HEADS  = 12;
static constexpr int LAYERS = 12;
static constexpr int NTOK   = 785;
static constexpr int NPATCH = 784;
static constexpr int MTOK   = BATCH * NTOK;    // 6280
static constexpr int MPATCH = BATCH * NPATCH;  // 6272
static constexpr int IMG    = 448;
static constexpr int PSZ    = 16;
static constexpr int GRID28 = 28;
static constexpr int SPAD   = 832;             // padded K-stride for probs/vT (13*64)
static constexpr long long LW = 7077888LL;     // per-layer transposed-weight stride

// ---------------- device scratch ----------------
__device__ bf16  g_phi[(size_t)MPATCH * DM];
__device__ bf16  g_plo[(size_t)MPATCH * DM];
__device__ bf16  g_cwhi[DM * DM];
__device__ bf16  g_cwlo[DM * DM];
__device__ bf16  g_whi[(size_t)LAYERS * LW];
__device__ bf16  g_wlo[(size_t)LAYERS * LW];
__device__ float g_h[(size_t)MTOK * DM];
__device__ float g_scores[(size_t)BATCH * HEADS * NTOK * NTOK];  // also fp32 patch temp
__device__ bf16  g_yhi[(size_t)MTOK * DM];
__device__ bf16  g_ylo[(size_t)MTOK * DM];
__device__ bf16  g_qhi[(size_t)MTOK * 3 * DM];
__device__ bf16  g_qlo[(size_t)MTOK * 3 * DM];
__device__ bf16  g_mhi[(size_t)MTOK * 4 * DM];
__device__ bf16  g_mlo[(size_t)MTOK * 4 * DM];
__device__ bf16  g_shi[(size_t)BATCH * HEADS * NTOK * SPAD];
__device__ bf16  g_slo[(size_t)BATCH * HEADS * NTOK * SPAD];
__device__ bf16  g_vthi[(size_t)BATCH * HEADS * 64 * SPAD];
__device__ bf16  g_vtlo[(size_t)BATCH * HEADS * 64 * SPAD];

// ---------------- small helpers ----------------
__device__ __forceinline__ void split2(float v, bf16& h, bf16& l) {
    h = __float2bfloat16(v);
    l = __float2bfloat16(v - __bfloat162float(h));
}
__device__ __forceinline__ float geluf(float v) {
    return 0.5f * v * (1.0f + erff(v * 0.70710678118654752f));
}
__device__ __forceinline__ float warpSum(float v) {
#pragma unroll
    for (int o = 16; o > 0; o >>= 1) v += __shfl_xor_sync(0xffffffffu, v, o);
    return v;
}
__device__ __forceinline__ float warpMax(float v) {
#pragma unroll
    for (int o = 16; o > 0; o >>= 1) v = fmaxf(v, __shfl_xor_sync(0xffffffffu, v, o));
    return v;
}
__device__ __forceinline__ float blockSum256(float v, float* sh) {
    int lane = threadIdx.x & 31, w = threadIdx.x >> 5;
    v = warpSum(v);
    if (lane == 0) sh[w] = v;
    __syncthreads();
    float r = (threadIdx.x < 8) ? sh[threadIdx.x] : 0.f;
    if (w == 0) { r = warpSum(r); if (lane == 0) sh[0] = r; }
    __syncthreads();
    r = sh[0];
    __syncthreads();
    return r;
}
__device__ __forceinline__ float blockMax256(float v, float* sh) {
    int lane = threadIdx.x & 31, w = threadIdx.x >> 5;
    v = warpMax(v);
    if (lane == 0) sh[w] = v;
    __syncthreads();
    float r = (threadIdx.x < 8) ? sh[threadIdx.x] : -1e30f;
    if (w == 0) { r = warpMax(r); if (lane == 0) sh[0] = r; }
    __syncthreads();
    r = sh[0];
    __syncthreads();
    return r;
}

// ---------------- PTX wrappers (plain sm_103-legal only) ----------------
__device__ __forceinline__ uint32_t s2u(const void* p) {
    uint32_t a;
    asm("{ .reg .u64 t; cvta.to.shared.u64 t, %1; cvt.u32.u64 %0, t; }" : "=r"(a) : "l"(p));
    return a;
}
__device__ __forceinline__ void cp16(uint32_t d, const void* s, bool pred) {
    int sz = pred ? 16 : 0;
    asm volatile("cp.async.cg.shared.global [%0], [%1], 16, %2;" :: "r"(d), "l"(s), "r"(sz));
}
__device__ __forceinline__ void cpcommit() { asm volatile("cp.async.commit_group;" ::: "memory"); }
__device__ __forceinline__ void cpwait0()  { asm volatile("cp.async.wait_group 0;" ::: "memory"); }
__device__ __forceinline__ void cpwait1()  { asm volatile("cp.async.wait_group 1;" ::: "memory"); }
__device__ __forceinline__ void ldsm4(uint32_t* r, uint32_t addr) {
    asm volatile("ldmatrix.sync.aligned.m8n8.x4.shared.b16 {%0,%1,%2,%3}, [%4];"
                 : "=r"(r[0]), "=r"(r[1]), "=r"(r[2]), "=r"(r[3]) : "r"(addr));
}
__device__ __forceinline__ void mma16816(float* c, const uint32_t* a, const uint32_t* b) {
    asm volatile(
        "mma.sync.aligned.m16n8k16.row.col.f32.bf16.bf16.f32 "
        "{%0,%1,%2,%3}, {%4,%5,%6,%7}, {%8,%9}, {%0,%1,%2,%3};"
        : "+f"(c[0]), "+f"(c[1]), "+f"(c[2]), "+f"(c[3])
        : "r"(a[0]), "r"(a[1]), "r"(a[2]), "r"(a[3]), "r"(b[0]), "r"(b[1]));
}

// ---------------- elementwise / prep kernels ----------------
__global__ void im2col_split(const float* __restrict__ x, bf16* __restrict__ Ph,
                             bf16* __restrict__ Pl) {
    int idx = blockIdx.x * blockDim.x + threadIdx.x;
    if (idx >= MPATCH * DM) return;
    int k = idx % DM, m = idx / DM;
    int b = m / NPATCH, t = m % NPATCH;
    int py = t / GRID28, px = t % GRID28;
    int c = k >> 8, rem = k & 255, i = rem >> 4, j = rem & 15;
    size_t src = (((size_t)(b * 3 + c) * IMG) + (size_t)(py * PSZ + i)) * IMG + (px * PSZ + j);
    bf16 h, l;
    split2(x[src], h, l);
    Ph[idx] = h; Pl[idx] = l;
}

__global__ void split_kernel(const float* __restrict__ W, bf16* __restrict__ Oh,
                             bf16* __restrict__ Ol, int n) {
    int idx = blockIdx.x * blockDim.x + threadIdx.x;
    if (idx >= n) return;
    bf16 h, l;
    split2(W[idx], h, l);
    Oh[idx] = h; Ol[idx] = l;
}

// W[K,N] row-major -> out[n*K + k] (transpose + split), tiled
__global__ void wt_trans(const float* __restrict__ W, bf16* __restrict__ Oh,
                         bf16* __restrict__ Ol, int K, int N) {
    __shared__ float tile[32][33];
    int kb = blockIdx.y * 32, nb = blockIdx.x * 32;
    int tx = threadIdx.x, ty = threadIdx.y;  // 32 x 8
#pragma unroll
    for (int i = 0; i < 32; i += 8) {
        int k = kb + ty + i, n = nb + tx;
        tile[ty + i][tx] = (k < K && n < N) ? W[(size_t)k * N + n] : 0.f;
    }
    __syncthreads();
#pragma unroll
    for (int i = 0; i < 32; i += 8) {
        int n = nb + ty + i, k = kb + tx;
        if (n < N && k < K) {
            bf16 h, l;
            split2(tile[tx][ty + i], h, l);
            Oh[(size_t)n * K + k] = h;
            Ol[(size_t)n * K + k] = l;
        }
    }
}

__global__ void assemble_kernel(const float* __restrict__ tok, const float* __restrict__ cls,
                                const float* __restrict__ pos, float* __restrict__ H) {
    int idx = blockIdx.x * blockDim.x + threadIdx.x;
    if (idx >= MTOK * DM) return;
    int d = idx % DM;
    int r = idx / DM;
    int n = r % NTOK, b = r / NTOK;
    float v;
    if (n == 0) v = cls[d] + pos[d];
    else        v = tok[((size_t)b * NPATCH + (n - 1)) * DM + d] + pos[(size_t)n * DM + d];
    H[idx] = v;
}

__global__ void ln_kernel(const float* __restrict__ X, const float* __restrict__ g,
                          const float* __restrict__ bb, float* __restrict__ Y,
                          long long inStride, long long outStride) {
    const float* x = X + (long long)blockIdx.x * inStride;
    float* y = Y + (long long)blockIdx.x * outStride;
    int t = threadIdx.x;
    __shared__ float sh[8];
    float v0 = x[t], v1 = x[t + 256], v2 = x[t + 512];
    float mu = blockSum256(v0 + v1 + v2, sh) * (1.0f / 768.0f);
    float d0 = v0 - mu, d1 = v1 - mu, d2 = v2 - mu;
    float var = blockSum256(d0 * d0 + d1 * d1 + d2 * d2, sh) * (1.0f / 768.0f);
    float rs = rsqrtf(var + 1e-5f);
    y[t]       = d0 * rs * g[t]       + bb[t];
    y[t + 256] = d1 * rs * g[t + 256] + bb[t + 256];
    y[t + 512] = d2 * rs * g[t + 512] + bb[t + 512];
}

__global__ void ln_split(const float* __restrict__ X, const float* __restrict__ g,
                         const float* __restrict__ bb, bf16* __restrict__ Yh,
                         bf16* __restrict__ Yl) {
    const float* x = X + (size_t)blockIdx.x * DM;
    bf16* yh = Yh + (size_t)blockIdx.x * DM;
    bf16* yl = Yl + (size_t)blockIdx.x * DM;
    int t = threadIdx.x;
    __shared__ float sh[8];
    float v0 = x[t], v1 = x[t + 256], v2 = x[t + 512];
    float mu = blockSum256(v0 + v1 + v2, sh) * (1.0f / 768.0f);
    float d0 = v0 - mu, d1 = v1 - mu, d2 = v2 - mu;
    float var = blockSum256(d0 * d0 + d1 * d1 + d2 * d2, sh) * (1.0f / 768.0f);
    float rs = rsqrtf(var + 1e-5f);
    float o0 = d0 * rs * g[t] + bb[t];
    float o1 = d1 * rs * g[t + 256] + bb[t + 256];
    float o2 = d2 * rs * g[t + 512] + bb[t + 512];
    bf16 h, l;
    split2(o0, h, l); yh[t] = h;       yl[t] = l;
    split2(o1, h, l); yh[t + 256] = h; yl[t + 256] = l;
    split2(o2, h, l); yh[t + 512] = h; yl[t + 512] = l;
}

__global__ void softmax_split(const float* __restrict__ S, bf16* __restrict__ Ph,
                              bf16* __restrict__ Pl) {
    const float* row = S + (size_t)blockIdx.x * NTOK;
    bf16* ph = Ph + (size_t)blockIdx.x * SPAD;
    bf16* pl = Pl + (size_t)blockIdx.x * SPAD;
    int t = threadIdx.x;
    __shared__ float sh[8];
    float v0 = row[t], v1 = row[t + 256], v2 = row[t + 512];
    float v3 = (t < NTOK - 768) ? row[t + 768] : -1e30f;
    float mx = blockMax256(fmaxf(fmaxf(v0, v1), fmaxf(v2, v3)), sh);
    float e0 = expf(v0 - mx), e1 = expf(v1 - mx), e2 = expf(v2 - mx);
    float e3 = (t < NTOK - 768) ? expf(v3 - mx) : 0.f;
    float s = blockSum256(e0 + e1 + e2 + e3, sh);
    float inv = 1.0f / s;
    bf16 h, l;
    split2(e0 * inv, h, l); ph[t] = h;       pl[t] = l;
    split2(e1 * inv, h, l); ph[t + 256] = h; pl[t + 256] = l;
    split2(e2 * inv, h, l); ph[t + 512] = h; pl[t + 512] = l;
    if (t < NTOK - 768) { split2(e3 * inv, h, l); ph[t + 768] = h; pl[t + 768] = l; }
    if (t < SPAD - NTOK) {
        bf16 z = __float2bfloat16(0.f);
        ph[NTOK + t] = z; pl[NTOK + t] = z;
    }
}

// vT[z][d][t] = qkv[b*785+t][1536 + h*64 + d], zero tail in t
__global__ void vt_split(const bf16* __restrict__ Qh, const bf16* __restrict__ Ql,
                         bf16* __restrict__ Vh, bf16* __restrict__ Vl) {
    size_t idx = (size_t)blockIdx.x * blockDim.x + threadIdx.x;
    if (idx >= (size_t)BATCH * HEADS * 64 * SPAD) return;
    int t = (int)(idx % SPAD);
    int d = (int)((idx / SPAD) % 64);
    int z = (int)(idx / ((size_t)SPAD * 64));
    int b = z / HEADS, h = z % HEADS;
    bf16 vh = __float2bfloat16(0.f), vl = vh;
    if (t < NTOK) {
        size_t src = ((size_t)(b * NTOK + t)) * (3 * DM) + 2 * DM + h * 64 + d;
        vh = Qh[src]; vl = Ql[src];
    }
    Vh[idx] = vh; Vl[idx] = vl;
}

// ---------------- HMMA (mma.sync bf16) split GEMM ----------------
// C[m,n] = alpha * sum_k (Ahi+Alo)[m,k]*(Bhi+Blo)[n,k], 3-term split.
// BM=128, BK=64, double-buffered cp.async, 8 warps. K must be a multiple of 64.
// EPI: 0 fp32 (+bias?+res?), 1 split bf16 (+bias?), 2 split gelu(+bias)
template <int BN, int EPI>
__global__ void __launch_bounds__(256, 1)
hmma_gemm(const bf16* __restrict__ Ahi_, const bf16* __restrict__ Alo_, int lda,
          const bf16* __restrict__ Bhi_, const bf16* __restrict__ Blo_, int ldb,
          float* __restrict__ Cf_, bf16* __restrict__ Chi_, bf16* __restrict__ Clo_, int ldc,
          const float* __restrict__ bias, const float* __restrict__ res_,
          int M, int N, int NC, int zdiv,
          long long sAo, long long sAi, long long sBo, long long sBi,
          long long sCo, long long sCi, float alpha) {
    constexpr int WGN = (BN == 128) ? 4 : 2;     // warps along N
    constexpr int WGM = 8 / WGN;                 // warps along M
    constexpr int WM  = 128 / WGM;               // 64 or 32
    constexpr int MT  = WM / 16;                 // 4 or 2
    constexpr int RS  = 144;                     // smem row stride bytes (64 bf16 + 8 pad)
    constexpr int ASZ = 128 * RS;
    constexpr int BSZ = BN * RS;
    constexpr int BUF = 2 * ASZ + 2 * BSZ;

    extern __shared__ __align__(16) char smem[];
    uint32_t s0 = s2u(smem);

    const int tid = threadIdx.x, lane = tid & 31, warp = tid >> 5;
    const int wm0 = (warp / WGN) * WM;
    const int wn0 = (warp % WGN) * 32;

    long long z = blockIdx.z;
    long long zo = z / zdiv, zi = z % zdiv;
    const bf16* Ahi = Ahi_ + zo * sAo + zi * sAi;
    const bf16* Alo = Alo_ + zo * sAo + zi * sAi;
    const bf16* Bhi = Bhi_ + zo * sBo + zi * sBi;
    const bf16* Blo = Blo_ + zo * sBo + zi * sBi;
    long long coff = zo * sCo + zi * sCi;
    float* Cf = Cf_ ? Cf_ + coff : nullptr;
    const float* res = res_ ? res_ + coff : nullptr;
    bf16* Chi = Chi_ ? Chi_ + coff : nullptr;
    bf16* Clo = Clo_ ? Clo_ + coff : nullptr;

    const int row0 = blockIdx.y * 128, col0 = blockIdx.x * BN;

    float acc[MT][4][4];
#pragma unroll
    for (int i = 0; i < MT; i++)
#pragma unroll
        for (int j = 0; j < 4; j++)
#pragma unroll
            for (int k = 0; k < 4; k++) acc[i][j][k] = 0.f;

    // per-lane ldmatrix base offsets
    const uint32_t a_lane = (uint32_t)(wm0 + (lane & 15)) * RS + (uint32_t)(lane >> 4) * 16u;
    const uint32_t b_lane = (uint32_t)(wn0 + (lane & 7) + ((lane >> 4) << 3)) * RS +
                            (uint32_t)((lane >> 3) & 1) * 16u;

    auto load_chunk = [&](int ck, int bsel) {
        uint32_t base = s0 + bsel * BUF;
        // A hi/lo: 128 rows x 8 granules
#pragma unroll
        for (int i = 0; i < 4; i++) {
            int idx = tid + i * 256;
            int r = idx >> 3, c = idx & 7;
            int gm = row0 + r;
            bool v = gm < M;
            const bf16* ph = v ? (Ahi + (size_t)gm * lda + (size_t)ck * 64 + c * 8) : Ahi;
            const bf16* pl = v ? (Alo + (size_t)gm * lda + (size_t)ck * 64 + c * 8) : Alo;
            uint32_t d = base + (uint32_t)r * RS + (uint32_t)c * 16u;
            cp16(d, ph, v);
            cp16(d + ASZ, pl, v);
        }
        // B hi/lo: BN rows x 8 granules
#pragma unroll
        for (int i = 0; i < BN / 32; i++) {
            int idx = tid + i * 256;
            int r = idx >> 3, c = idx & 7;
            int gn = col0 + r;
            bool v = gn < N;
            const bf16* ph = v ? (Bhi + (size_t)gn * ldb + (size_t)ck * 64 + c * 8) : Bhi;
            const bf16* pl = v ? (Blo + (size_t)gn * ldb + (size_t)ck * 64 + c * 8) : Blo;
            uint32_t d = base + 2 * ASZ + (uint32_t)r * RS + (uint32_t)c * 16u;
            cp16(d, ph, v);
            cp16(d + BSZ, pl, v);
        }
        cpcommit();
    };

    auto compute = [&](int bsel) {
        uint32_t base = s0 + bsel * BUF;
        uint32_t ah = base, al = base + ASZ, bh = base + 2 * ASZ, bl = base + 2 * ASZ + BSZ;
#pragma unroll
        for (int ks = 0; ks < 4; ks++) {
            uint32_t afh[MT][4], afl[MT][4];
#pragma unroll
            for (int mt = 0; mt < MT; mt++) {
                uint32_t off = a_lane + (uint32_t)mt * (16 * RS) + (uint32_t)ks * 32u;
                ldsm4(afh[mt], ah + off);
                ldsm4(afl[mt], al + off);
            }
            uint32_t bfh[2][4], bfl[2][4];
#pragma unroll
            for (int np = 0; np < 2; np++) {
                uint32_t off = b_lane + (uint32_t)np * (16 * RS) + (uint32_t)ks * 32u;
                ldsm4(bfh[np], bh + off);
                ldsm4(bfl[np], bl + off);
            }
#pragma unroll
            for (int mt = 0; mt < MT; mt++)
#pragma unroll
                for (int nt = 0; nt < 4; nt++) {
                    const uint32_t* Bh2 = &bfh[nt >> 1][(nt & 1) * 2];
                    const uint32_t* Bl2 = &bfl[nt >> 1][(nt & 1) * 2];
                    mma16816(acc[mt][nt], afh[mt], Bh2);
                    mma16816(acc[mt][nt], afh[mt], Bl2);
                    mma16816(acc[mt][nt], afl[mt], Bh2);
                }
        }
    };

    load_chunk(0, 0);
    for (int ck = 0; ck < NC; ck++) {
        if (ck + 1 < NC) { load_chunk(ck + 1, (ck + 1) & 1); cpwait1(); }
        else             { cpwait0(); }
        __syncthreads();
        compute(ck & 1);
        __syncthreads();
    }

    // epilogue
#pragma unroll
    for (int mt = 0; mt < MT; mt++) {
#pragma unroll
        for (int nt = 0; nt < 4; nt++) {
            int r0 = row0 + wm0 + mt * 16 + (lane >> 2);
            int c0 = col0 + wn0 + nt * 8 + (lane & 3) * 2;
            float* a4 = acc[mt][nt];
            if (EPI == 0) {
#pragma unroll
                for (int h = 0; h < 2; h++) {
                    int gm = r0 + h * 8;
                    if (gm >= M) continue;
#pragma unroll
                    for (int q = 0; q < 2; q++) {
                        int gn = c0 + q;
                        if (gn >= N) continue;
                        float v = a4[h * 2 + q] * alpha;
                        if (bias) v += bias[gn];
                        if (res)  v += res[(size_t)gm * ldc + gn];
                        Cf[(size_t)gm * ldc + gn] = v;
                    }
                }
            } else {
#pragma unroll
                for (int h = 0; h < 2; h++) {
                    int gm = r0 + h * 8;
                    if (gm >= M) continue;
                    float v0 = a4[h * 2], v1 = a4[h * 2 + 1];
                    if (bias) { v0 += bias[c0]; v1 += bias[c0 + 1]; }
                    if (EPI == 2) { v0 = geluf(v0); v1 = geluf(v1); }
                    bf16 h0, l0, h1, l1;
                    split2(v0, h0, l0);
                    split2(v1, h1, l1);
                    __nv_bfloat162 hh; hh.x = h0; hh.y = h1;
                    __nv_bfloat162 ll; ll.x = l0; ll.y = l1;
                    *(__nv_bfloat162*)(Chi + (size_t)gm * ldc + c0) = hh;
                    *(__nv_bfloat162*)(Clo + (size_t)gm * ldc + c0) = ll;
                }
            }
        }
    }
}

// ---------------- host-side GEMM launcher ----------------
template <int BN, int EPI>
static void ggemm(const bf16* Ah, const bf16* Al, int lda,
                  const bf16* Bh, const bf16* Bl, int ldb,
                  float* Cf, bf16* Ch, bf16* Cl, int ldc,
                  const float* bias, const float* res,
                  int M, int N, int K, int Z, int zdiv,
                  long long sAo, long long sAi, long long sBo, long long sBi,
                  long long sCo, long long sCi, float alpha) {
    constexpr int RS = 144;
    constexpr int BUF = 2 * 128 * RS + 2 * BN * RS;
    int smem = 2 * BUF;
    cudaFuncSetAttribute(hmma_gemm<BN, EPI>, cudaFuncAttributeMaxDynamicSharedMemorySize, smem);
    dim3 grid((N + BN - 1) / BN, (M + 127) / 128, Z);
    hmma_gemm<BN, EPI><<<grid, 256, smem>>>(Ah, Al, lda, Bh, Bl, ldb, Cf, Ch, Cl, ldc,
                                            bias, res, M, N, K / 64, zdiv,
                                            sAo, sAi, sBo, sBi, sCo, sCi, alpha);
}

extern "C" void kernel_launch(void* const* d_in, const int* in_sizes, int n_in,
                              void* d_out, int out_size) {
    const float* x       = (const float*)d_in[0];
    const float* conv_w  = (const float*)d_in[1];
    const float* conv_b  = (const float*)d_in[2];
    const float* cls_tok = (const float*)d_in[3];
    const float* pos_emb = (const float*)d_in[4];
    const float* ln1_g   = (const float*)d_in[5];
    const float* ln1_b   = (const float*)d_in[6];
    const float* qkv_w   = (const float*)d_in[7];
    const float* qkv_b   = (const float*)d_in[8];
    const float* proj_w  = (const float*)d_in[9];
    const float* proj_b  = (const float*)d_in[10];
    const float* ln2_g   = (const float*)d_in[11];
    const float* ln2_b   = (const float*)d_in[12];
    const float* mlp_w1  = (const float*)d_in[13];
    const float* mlp_b1  = (const float*)d_in[14];
    const float* mlp_w2  = (const float*)d_in[15];
    const float* mlp_b2  = (const float*)d_in[16];
    const float* lnf_g   = (const float*)d_in[17];
    const float* lnf_b   = (const float*)d_in[18];
    float* out = (float*)d_out;

    bf16 *phi, *plo, *cwhi, *cwlo, *whi, *wlo, *yhi, *ylo, *qhi, *qlo, *mhi, *mlo,
         *shi, *slo, *vthi, *vtlo;
    float *ph, *pscores;
    cudaGetSymbolAddress((void**)&phi, g_phi);
    cudaGetSymbolAddress((void**)&plo, g_plo);
    cudaGetSymbolAddress((void**)&cwhi, g_cwhi);
    cudaGetSymbolAddress((void**)&cwlo, g_cwlo);
    cudaGetSymbolAddress((void**)&whi, g_whi);
    cudaGetSymbolAddress((void**)&wlo, g_wlo);
    cudaGetSymbolAddress((void**)&ph, g_h);
    cudaGetSymbolAddress((void**)&pscores, g_scores);
    cudaGetSymbolAddress((void**)&yhi, g_yhi);
    cudaGetSymbolAddress((void**)&ylo, g_ylo);
    cudaGetSymbolAddress((void**)&qhi, g_qhi);
    cudaGetSymbolAddress((void**)&qlo, g_qlo);
    cudaGetSymbolAddress((void**)&mhi, g_mhi);
    cudaGetSymbolAddress((void**)&mlo, g_mlo);
    cudaGetSymbolAddress((void**)&shi, g_shi);
    cudaGetSymbolAddress((void**)&slo, g_slo);
    cudaGetSymbolAddress((void**)&vthi, g_vthi);
    cudaGetSymbolAddress((void**)&vtlo, g_vtlo);

    dim3 tb(32, 8);

    // ---- weight prep ----
    split_kernel<<<(DM * DM + 255) / 256, 256>>>(conv_w, cwhi, cwlo, DM * DM);
    for (int l = 0; l < LAYERS; l++) {
        long long wo = (long long)l * LW;
        wt_trans<<<dim3(2304 / 32, 768 / 32), tb>>>(qkv_w + (size_t)l * DM * 3 * DM,
                                                    whi + wo, wlo + wo, DM, 3 * DM);
        wt_trans<<<dim3(768 / 32, 768 / 32), tb>>>(proj_w + (size_t)l * DM * DM,
                                                   whi + wo + 1769472, wlo + wo + 1769472, DM, DM);
        wt_trans<<<dim3(3072 / 32, 768 / 32), tb>>>(mlp_w1 + (size_t)l * DM * 4 * DM,
                                                    whi + wo + 2359296, wlo + wo + 2359296, DM, 4 * DM);
        wt_trans<<<dim3(768 / 32, 3072 / 32), tb>>>(mlp_w2 + (size_t)l * 4 * DM * DM,
                                                    whi + wo + 4718592, wlo + wo + 4718592, 4 * DM, DM);
    }

    // ---- patch embed ----
    im2col_split<<<(MPATCH * DM + 255) / 256, 256>>>(x, phi, plo);
    ggemm<128, 0>(phi, plo, DM, cwhi, cwlo, DM, pscores, nullptr, nullptr, DM,
                  conv_b, nullptr, MPATCH, DM, DM, 1, 1, 0, 0, 0, 0, 0, 0, 1.0f);
    assemble_kernel<<<(MTOK * DM + 255) / 256, 256>>>(pscores, cls_tok, pos_emb, ph);

    const float attn_scale = 0.125f;
    const long long sQb = (long long)NTOK * 3 * DM;
    const long long sSb = (long long)HEADS * NTOK * NTOK;
    const long long sSi = (long long)NTOK * NTOK;
    const long long sPb = (long long)HEADS * NTOK * SPAD;
    const long long sPi = (long long)NTOK * SPAD;
    const long long sVb = (long long)HEADS * 64 * SPAD;
    const long long sVi = (long long)64 * SPAD;

    for (int l = 0; l < LAYERS; l++) {
        long long wo = (long long)l * LW;
        const bf16* qwT_h = whi + wo;            const bf16* qwT_l = wlo + wo;
        const bf16* pwT_h = whi + wo + 1769472;  const bf16* pwT_l = wlo + wo + 1769472;
        const bf16* w1T_h = whi + wo + 2359296;  const bf16* w1T_l = wlo + wo + 2359296;
        const bf16* w2T_h = whi + wo + 4718592;  const bf16* w2T_l = wlo + wo + 4718592;
        const float* l1g = ln1_g + (size_t)l * DM;
        const float* l1b = ln1_b + (size_t)l * DM;
        const float* qb  = qkv_b + (size_t)l * 3 * DM;
        const float* pb  = proj_b + (size_t)l * DM;
        const float* l2g = ln2_g + (size_t)l * DM;
        const float* l2b = ln2_b + (size_t)l * DM;
        const float* b1  = mlp_b1 + (size_t)l * 4 * DM;
        const float* b2  = mlp_b2 + (size_t)l * DM;

        // LN1 -> split y
        ln_split<<<MTOK, 256>>>(ph, l1g, l1b, yhi, ylo);
        // QKV
        ggemm<128, 1>(yhi, ylo, DM, qwT_h, qwT_l, DM, nullptr, qhi, qlo, 3 * DM,
                      qb, nullptr, MTOK, 3 * DM, DM, 1, 1, 0, 0, 0, 0, 0, 0, 1.0f);
        // V transpose
        {
            size_t n = (size_t)BATCH * HEADS * 64 * SPAD;
            vt_split<<<(unsigned)((n + 255) / 256), 256>>>(qhi, qlo, vthi, vtlo);
        }
        // QK^T per (b,h) -> fp32 scores
        ggemm<128, 0>(qhi, qlo, 3 * DM, qhi + DM, qlo + DM, 3 * DM,
                      pscores, nullptr, nullptr, NTOK, nullptr, nullptr,
                      NTOK, NTOK, 64, BATCH * HEADS, HEADS,
                      sQb, 64, sQb, 64, sSb, sSi, attn_scale);
        // softmax -> split probs (padded)
        softmax_split<<<BATCH * HEADS * NTOK, 256>>>(pscores, shi, slo);
        // S @ V^T -> y at column h*64
        ggemm<64, 1>(shi, slo, SPAD, vthi, vtlo, SPAD,
                     nullptr, yhi, ylo, DM, nullptr, nullptr,
                     NTOK, 64, SPAD, BATCH * HEADS, HEADS,
                     sPb, sPi, sVb, sVi, (long long)NTOK * DM, 64, 1.0f);
        // proj + bias + residual
        ggemm<128, 0>(yhi, ylo, DM, pwT_h, pwT_l, DM, ph, nullptr, nullptr, DM,
                      pb, ph, MTOK, DM, DM, 1, 1, 0, 0, 0, 0, 0, 0, 1.0f);
        // LN2 -> split y
        ln_split<<<MTOK, 256>>>(ph, l2g, l2b, yhi, ylo);
        // MLP1 + gelu
        ggemm<128, 2>(yhi, ylo, DM, w1T_h, w1T_l, DM, nullptr, mhi, mlo, 4 * DM,
                      b1, nullptr, MTOK, 4 * DM, DM, 1, 1, 0, 0, 0, 0, 0, 0, 1.0f);
        // MLP2 + bias + residual
        ggemm<128, 0>(mhi, mlo, 4 * DM, w2T_h, w2T_l, 4 * DM, ph, nullptr, nullptr, DM,
                      b2, ph, MTOK, DM, 4 * DM, 1, 1, 0, 0, 0, 0, 0, 0, 1.0f);
    }

    // final LN on CLS rows -> out [8,768]
    ln_kernel<<<BATCH, 256>>>(ph, lnf_g, lnf_b, out, (long long)NTOK * DM, DM);
}

// round 7
// speedup vs baseline: 2.3806x; 1.0851x over previous
#include <cuda_runtime.h>
#include <cuda_bf16.h>
#include <math.h>
#include <stdint.h>

using bf16 = __nv_bfloat16;

// ---------------- problem constants ----------------
static constexpr int BATCH  = 8;
static constexpr int DM     = 768;
static constexpr int HEADS  = 12;
static constexpr int LAYERS = 12;
static constexpr int NTOK   = 785;
static constexpr int NPATCH = 784;
static constexpr int MTOK   = BATCH * NTOK;    // 6280
static constexpr int MPATCH = BATCH * NPATCH;  // 6272
static constexpr int IMG    = 448;
static constexpr int PSZ    = 16;
static constexpr int GRID28 = 28;
static constexpr int SPAD   = 896;             // padded token stride for vT (7*128)
static constexpr long long LW = 7077888LL;     // per-layer transposed-weight stride

// ---------------- device scratch ----------------
__device__ bf16  g_phi[(size_t)MPATCH * DM];
__device__ bf16  g_plo[(size_t)MPATCH * DM];
__device__ bf16  g_cwhi[DM * DM];
__device__ bf16  g_cwlo[DM * DM];
__device__ bf16  g_whi[(size_t)LAYERS * LW];
__device__ bf16  g_wlo[(size_t)LAYERS * LW];
__device__ float g_h[(size_t)MTOK * DM];
__device__ float g_ptmp[(size_t)MPATCH * DM];   // fp32 patch temp
__device__ bf16  g_yhi[(size_t)MTOK * DM];
__device__ bf16  g_ylo[(size_t)MTOK * DM];
__device__ bf16  g_qhi[(size_t)MTOK * 3 * DM];
__device__ bf16  g_qlo[(size_t)MTOK * 3 * DM];
__device__ bf16  g_mhi[(size_t)MTOK * 4 * DM];
__device__ bf16  g_mlo[(size_t)MTOK * 4 * DM];
__device__ bf16  g_vthi[(size_t)BATCH * HEADS * 64 * SPAD];
__device__ bf16  g_vtlo[(size_t)BATCH * HEADS * 64 * SPAD];

// ---------------- small helpers ----------------
__device__ __forceinline__ void split2(float v, bf16& h, bf16& l) {
    h = __float2bfloat16(v);
    l = __float2bfloat16(v - __bfloat162float(h));
}
__device__ __forceinline__ float geluf(float v) {
    return 0.5f * v * (1.0f + erff(v * 0.70710678118654752f));
}
__device__ __forceinline__ float warpSum(float v) {
#pragma unroll
    for (int o = 16; o > 0; o >>= 1) v += __shfl_xor_sync(0xffffffffu, v, o);
    return v;
}
__device__ __forceinline__ float blockSum256(float v, float* sh) {
    int lane = threadIdx.x & 31, w = threadIdx.x >> 5;
    v = warpSum(v);
    if (lane == 0) sh[w] = v;
    __syncthreads();
    float r = (threadIdx.x < 8) ? sh[threadIdx.x] : 0.f;
    if (w == 0) { r = warpSum(r); if (lane == 0) sh[0] = r; }
    __syncthreads();
    r = sh[0];
    __syncthreads();
    return r;
}

// ---------------- PTX wrappers (plain sm_103-legal only) ----------------
__device__ __forceinline__ uint32_t s2u(const void* p) {
    uint32_t a;
    asm("{ .reg .u64 t; cvta.to.shared.u64 t, %1; cvt.u32.u64 %0, t; }" : "=r"(a) : "l"(p));
    return a;
}
__device__ __forceinline__ void cp16(uint32_t d, const void* s, bool pred) {
    int sz = pred ? 16 : 0;
    asm volatile("cp.async.cg.shared.global [%0], [%1], 16, %2;" :: "r"(d), "l"(s), "r"(sz));
}
__device__ __forceinline__ void cpcommit() { asm volatile("cp.async.commit_group;" ::: "memory"); }
__device__ __forceinline__ void cpwait0()  { asm volatile("cp.async.wait_group 0;" ::: "memory"); }
__device__ __forceinline__ void cpwait1()  { asm volatile("cp.async.wait_group 1;" ::: "memory"); }
__device__ __forceinline__ void ldsm4(uint32_t* r, uint32_t addr) {
    asm volatile("ldmatrix.sync.aligned.m8n8.x4.shared.b16 {%0,%1,%2,%3}, [%4];"
                 : "=r"(r[0]), "=r"(r[1]), "=r"(r[2]), "=r"(r[3]) : "r"(addr));
}
__device__ __forceinline__ void mma16816(float* c, const uint32_t* a, const uint32_t* b) {
    asm volatile(
        "mma.sync.aligned.m16n8k16.row.col.f32.bf16.bf16.f32 "
        "{%0,%1,%2,%3}, {%4,%5,%6,%7}, {%8,%9}, {%0,%1,%2,%3};"
        : "+f"(c[0]), "+f"(c[1]), "+f"(c[2]), "+f"(c[3])
        : "r"(a[0]), "r"(a[1]), "r"(a[2]), "r"(a[3]), "r"(b[0]), "r"(b[1]));
}
__device__ __forceinline__ uint32_t packsplit_hi(float a, float b, uint32_t& lo) {
    bf16 ah, al, bh, bl;
    split2(a, ah, al);
    split2(b, bh, bl);
    __nv_bfloat162 h2; h2.x = ah; h2.y = bh;
    __nv_bfloat162 l2; l2.x = al; l2.y = bl;
    lo = *reinterpret_cast<uint32_t*>(&l2);
    return *reinterpret_cast<uint32_t*>(&h2);
}

// ---------------- elementwise / prep kernels ----------------
__global__ void im2col_split(const float* __restrict__ x, bf16* __restrict__ Ph,
                             bf16* __restrict__ Pl) {
    int idx = blockIdx.x * blockDim.x + threadIdx.x;
    if (idx >= MPATCH * DM) return;
    int k = idx % DM, m = idx / DM;
    int b = m / NPATCH, t = m % NPATCH;
    int py = t / GRID28, px = t % GRID28;
    int c = k >> 8, rem = k & 255, i = rem >> 4, j = rem & 15;
    size_t src = (((size_t)(b * 3 + c) * IMG) + (size_t)(py * PSZ + i)) * IMG + (px * PSZ + j);
    bf16 h, l;
    split2(x[src], h, l);
    Ph[idx] = h; Pl[idx] = l;
}

__global__ void split_kernel(const float* __restrict__ W, bf16* __restrict__ Oh,
                             bf16* __restrict__ Ol, int n) {
    int idx = blockIdx.x * blockDim.x + threadIdx.x;
    if (idx >= n) return;
    bf16 h, l;
    split2(W[idx], h, l);
    Oh[idx] = h; Ol[idx] = l;
}

// W[K,N] row-major -> out[n*K + k] (transpose + split), tiled
__global__ void wt_trans(const float* __restrict__ W, bf16* __restrict__ Oh,
                         bf16* __restrict__ Ol, int K, int N) {
    __shared__ float tile[32][33];
    int kb = blockIdx.y * 32, nb = blockIdx.x * 32;
    int tx = threadIdx.x, ty = threadIdx.y;  // 32 x 8
#pragma unroll
    for (int i = 0; i < 32; i += 8) {
        int k = kb + ty + i, n = nb + tx;
        tile[ty + i][tx] = (k < K && n < N) ? W[(size_t)k * N + n] : 0.f;
    }
    __syncthreads();
#pragma unroll
    for (int i = 0; i < 32; i += 8) {
        int n = nb + ty + i, k = kb + tx;
        if (n < N && k < K) {
            bf16 h, l;
            split2(tile[tx][ty + i], h, l);
            Oh[(size_t)n * K + k] = h;
            Ol[(size_t)n * K + k] = l;
        }
    }
}

__global__ void assemble_kernel(const float* __restrict__ tok, const float* __restrict__ cls,
                                const float* __restrict__ pos, float* __restrict__ H) {
    int idx = blockIdx.x * blockDim.x + threadIdx.x;
    if (idx >= MTOK * DM) return;
    int d = idx % DM;
    int r = idx / DM;
    int n = r % NTOK, b = r / NTOK;
    float v;
    if (n == 0) v = cls[d] + pos[d];
    else        v = tok[((size_t)b * NPATCH + (n - 1)) * DM + d] + pos[(size_t)n * DM + d];
    H[idx] = v;
}

__global__ void ln_kernel(const float* __restrict__ X, const float* __restrict__ g,
                          const float* __restrict__ bb, float* __restrict__ Y,
                          long long inStride, long long outStride) {
    const float* x = X + (long long)blockIdx.x * inStride;
    float* y = Y + (long long)blockIdx.x * outStride;
    int t = threadIdx.x;
    __shared__ float sh[8];
    float v0 = x[t], v1 = x[t + 256], v2 = x[t + 512];
    float mu = blockSum256(v0 + v1 + v2, sh) * (1.0f / 768.0f);
    float d0 = v0 - mu, d1 = v1 - mu, d2 = v2 - mu;
    float var = blockSum256(d0 * d0 + d1 * d1 + d2 * d2, sh) * (1.0f / 768.0f);
    float rs = rsqrtf(var + 1e-5f);
    y[t]       = d0 * rs * g[t]       + bb[t];
    y[t + 256] = d1 * rs * g[t + 256] + bb[t + 256];
    y[t + 512] = d2 * rs * g[t + 512] + bb[t + 512];
}

__global__ void ln_split(const float* __restrict__ X, const float* __restrict__ g,
                         const float* __restrict__ bb, bf16* __restrict__ Yh,
                         bf16* __restrict__ Yl) {
    const float* x = X + (size_t)blockIdx.x * DM;
    bf16* yh = Yh + (size_t)blockIdx.x * DM;
    bf16* yl = Yl + (size_t)blockIdx.x * DM;
    int t = threadIdx.x;
    __shared__ float sh[8];
    float v0 = x[t], v1 = x[t + 256], v2 = x[t + 512];
    float mu = blockSum256(v0 + v1 + v2, sh) * (1.0f / 768.0f);
    float d0 = v0 - mu, d1 = v1 - mu, d2 = v2 - mu;
    float var = blockSum256(d0 * d0 + d1 * d1 + d2 * d2, sh) * (1.0f / 768.0f);
    float rs = rsqrtf(var + 1e-5f);
    float o0 = d0 * rs * g[t] + bb[t];
    float o1 = d1 * rs * g[t + 256] + bb[t + 256];
    float o2 = d2 * rs * g[t + 512] + bb[t + 512];
    bf16 h, l;
    split2(o0, h, l); yh[t] = h;       yl[t] = l;
    split2(o1, h, l); yh[t + 256] = h; yl[t + 256] = l;
    split2(o2, h, l); yh[t + 512] = h; yl[t + 512] = l;
}

// vT[z][d][t] = qkv[b*785+t][1536 + h*64 + d], zero tail in t  (validated round 4)
__global__ void vt_split(const bf16* __restrict__ Qh, const bf16* __restrict__ Ql,
                         bf16* __restrict__ Vh, bf16* __restrict__ Vl) {
    size_t idx = (size_t)blockIdx.x * blockDim.x + threadIdx.x;
    if (idx >= (size_t)BATCH * HEADS * 64 * SPAD) return;
    int t = (int)(idx % SPAD);
    int d = (int)((idx / SPAD) % 64);
    int z = (int)(idx / ((size_t)SPAD * 64));
    int b = z / HEADS, h = z % HEADS;
    bf16 vh = __float2bfloat16(0.f), vl = vh;
    if (t < NTOK) {
        size_t src = ((size_t)(b * NTOK + t)) * (3 * DM) + 2 * DM + h * 64 + d;
        vh = Qh[src]; vl = Ql[src];
    }
    Vh[idx] = vh; Vl[idx] = vl;
}

// ---------------- fused flash attention v3 (coordinate-free softmax) ----------------
// One block = 128 query rows of one (b,h). 8 warps x 16 rows.
// S frags -> smem fp32 via validated epilogue coords; softmax is purely linear
// (2 threads per row, 64 contiguous cols each); P packed linearly; P reloaded
// as A-frags; V via pre-transposed VT (validated B path). Single-buffered K/V.
static constexpr int ARS    = 144;              // K/Q tile row stride  [128 x 64]
static constexpr int KTILE  = 128 * ARS;        // 18432
static constexpr int VRS    = 272;              // VT tile row stride   [64 x 128]
static constexpr int VTILE  = 64 * VRS;         // 17408
static constexpr int SRS_F  = 132;              // S row stride (floats)
static constexpr int PRS    = 272;              // P tile row stride (bytes)
static constexpr int OFF_KH = 0;
static constexpr int OFF_KL = OFF_KH + KTILE;          // 18432
static constexpr int OFF_VH = OFF_KL + KTILE;          // 36864
static constexpr int OFF_VL = OFF_VH + VTILE;          // 54272
static constexpr int OFF_S  = OFF_VL + VTILE;          // 71680  (S fp32: 128*132*4 = 67584)
static constexpr int OFF_PH = OFF_S + 128 * SRS_F * 4; // 139264
static constexpr int OFF_PL = OFF_PH + 128 * PRS;      // 174080
static constexpr int OFF_M  = OFF_PL + 128 * PRS;      // 208896
static constexpr int OFF_L  = OFF_M + 512;             // 209408
static constexpr int OFF_CA = OFF_L + 512;             // 209920
static constexpr int OFF_T  = OFF_CA + 512;            // 210432 (tmax 256*4)
static constexpr int FA_SMEM = OFF_T + 1024;           // 211456
static constexpr int NCHUNK = 7;

__global__ void __launch_bounds__(256, 1)
fused_attn(const bf16* __restrict__ qkvh, const bf16* __restrict__ qkvl,
           const bf16* __restrict__ vth, const bf16* __restrict__ vtl,
           bf16* __restrict__ yh, bf16* __restrict__ yl) {
    extern __shared__ __align__(16) char smem[];
    uint32_t s0 = s2u(smem);
    const int tid = threadIdx.x, lane = tid & 31, warp = tid >> 5;
    const int qt = blockIdx.x;                 // 0..6
    const int z = blockIdx.y;                  // 0..95
    const int b = z / HEADS, h = z % HEADS;
    const float SC = 0.125f;

    const int wm0 = warp * 16;
    const uint32_t a_lane  = (uint32_t)(wm0 + (lane & 15)) * ARS + (uint32_t)(lane >> 4) * 16u;
    const uint32_t b_lane  = (uint32_t)((lane & 7) + ((lane >> 4) << 3)) * ARS +
                             (uint32_t)((lane >> 3) & 1) * 16u;
    const uint32_t vb_lane = (uint32_t)((lane & 7) + ((lane >> 4) << 3)) * VRS +
                             (uint32_t)((lane >> 3) & 1) * 16u;
    const uint32_t ap_lane = (uint32_t)(wm0 + (lane & 15)) * PRS + (uint32_t)(lane >> 4) * 16u;

    float* Sf   = reinterpret_cast<float*>(smem + OFF_S);
    float* mrow = reinterpret_cast<float*>(smem + OFF_M);
    float* lrow = reinterpret_cast<float*>(smem + OFF_L);
    float* crow = reinterpret_cast<float*>(smem + OFF_CA);
    float* tred = reinterpret_cast<float*>(smem + OFF_T);

    // load a [128x64] hi/lo pair from qkv into smem (identical pattern to gemm loader)
    auto load_qk = [&](int rowbase, int colbase, uint32_t dsth, uint32_t dstl) {
#pragma unroll
        for (int i = 0; i < 4; i++) {
            int idx = tid + i * 256;
            int r = idx >> 3, g = idx & 7;
            bool v = (rowbase + r) < NTOK;
            size_t off = ((size_t)(b * NTOK + rowbase + r)) * (3 * DM) + colbase + g * 8;
            const bf16* sh2 = v ? (qkvh + off) : qkvh;
            const bf16* sl2 = v ? (qkvl + off) : qkvl;
            uint32_t d = (uint32_t)r * ARS + (uint32_t)g * 16u;
            cp16(dsth + d, sh2, v);
            cp16(dstl + d, sl2, v);
        }
    };
    auto load_vt = [&](int c) {
        const bf16* bh2 = vth + (size_t)z * 64 * SPAD + (size_t)c * 128;
        const bf16* bl2 = vtl + (size_t)z * 64 * SPAD + (size_t)c * 128;
#pragma unroll
        for (int i = 0; i < 4; i++) {
            int idx = tid + i * 256;
            int r = idx >> 4, g = idx & 15;
            size_t off = (size_t)r * SPAD + g * 8;
            uint32_t d = (uint32_t)r * VRS + (uint32_t)g * 16u;
            cp16(s0 + OFF_VH + d, bh2 + off, true);
            cp16(s0 + OFF_VL + d, bl2 + off, true);
        }
    };

    // ---- stage Q (in S region), pull to registers ----
    load_qk(qt * 128, h * 64, s0 + OFF_S, s0 + OFF_S + KTILE);
    cpcommit();
    cpwait0();
    __syncthreads();
    uint32_t aQh[4][4], aQl[4][4];
#pragma unroll
    for (int ks = 0; ks < 4; ks++) {
        ldsm4(aQh[ks], s0 + OFF_S + a_lane + ks * 32);
        ldsm4(aQl[ks], s0 + OFF_S + KTILE + a_lane + ks * 32);
    }
    if (tid < 128) { mrow[tid] = -1e30f; lrow[tid] = 0.f; }
    __syncthreads();   // Q consumed; S region reusable; m/l ready

    float o[8][4];
#pragma unroll
    for (int i = 0; i < 8; i++)
#pragma unroll
        for (int j = 0; j < 4; j++) o[i][j] = 0.f;

    for (int c = 0; c < NCHUNK; c++) {
        // ---- load K + VT chunk (single-buffered) ----
        load_qk(c * 128, DM + h * 64, s0 + OFF_KH, s0 + OFF_KL);
        load_vt(c);
        cpcommit();
        cpwait0();
        __syncthreads();

        // ---- S = Q K^T (3-term split) ----
        float s[16][4];
#pragma unroll
        for (int j = 0; j < 16; j++)
#pragma unroll
            for (int q = 0; q < 4; q++) s[j][q] = 0.f;
#pragma unroll
        for (int ks = 0; ks < 4; ks++) {
#pragma unroll
            for (int jp = 0; jp < 8; jp++) {
                uint32_t kh[4], kl[4];
                uint32_t koff = b_lane + (uint32_t)jp * (16 * ARS) + (uint32_t)ks * 32u;
                ldsm4(kh, s0 + OFF_KH + koff);
                ldsm4(kl, s0 + OFF_KL + koff);
#pragma unroll
                for (int hf = 0; hf < 2; hf++) {
                    int j = jp * 2 + hf;
                    mma16816(s[j], aQh[ks], &kh[hf * 2]);
                    mma16816(s[j], aQh[ks], &kl[hf * 2]);
                    mma16816(s[j], aQl[ks], &kh[hf * 2]);
                }
            }
        }

        // ---- dump S to smem fp32 (validated EPI store coordinates) ----
        {
            int r0 = wm0 + (lane >> 2);
            int c0 = 2 * (lane & 3);
#pragma unroll
            for (int j = 0; j < 16; j++) {
                int cc = j * 8 + c0;
                Sf[r0 * SRS_F + cc]           = s[j][0];
                Sf[r0 * SRS_F + cc + 1]       = s[j][1];
                Sf[(r0 + 8) * SRS_F + cc]     = s[j][2];
                Sf[(r0 + 8) * SRS_F + cc + 1] = s[j][3];
            }
        }
        __syncthreads();

        // ---- linear softmax: row r = tid>>1, half = tid&1 owns 64 contiguous cols ----
        const int r = tid >> 1, half = tid & 1;
        const float* srow = Sf + r * SRS_F + half * 64;
        const int colbase = c * 128 + half * 64;
        const int nvalid0 = NTOK - colbase;  // cols [0, nvalid) are valid keys
        const int nvalid = nvalid0 < 0 ? 0 : (nvalid0 > 64 ? 64 : nvalid0);

        float chmax = -1e30f;
        for (int k = 0; k < nvalid; k++) chmax = fmaxf(chmax, srow[k]);
        tred[tid] = chmax;
        __syncthreads();
        float m_old = mrow[r];
        float rmax = fmaxf(tred[2 * r], tred[2 * r + 1]);
        float m_new = fmaxf(m_old, rmax);
        float ca = __expf(SC * (m_old - m_new));
        __syncthreads();  // tred free for reuse

        float esum = 0.f;
        {
            char* smp = smem;
            uint32_t prow = (uint32_t)r * PRS + (uint32_t)(half * 64) * 2u;
#pragma unroll 8
            for (int k = 0; k < 64; k += 2) {
                float e0 = (k < nvalid)     ? __expf(SC * (srow[k] - m_new))     : 0.f;
                float e1 = (k + 1 < nvalid) ? __expf(SC * (srow[k + 1] - m_new)) : 0.f;
                esum += e0 + e1;
                uint32_t lo, hi = packsplit_hi(e0, e1, lo);
                *(uint32_t*)(smp + OFF_PH + prow + k * 2) = hi;
                *(uint32_t*)(smp + OFF_PL + prow + k * 2) = lo;
            }
        }
        tred[tid] = esum;
        __syncthreads();
        if (half == 0) {
            lrow[r] = lrow[r] * ca + tred[2 * r] + tred[2 * r + 1];
            mrow[r] = m_new;
            crow[r] = ca;
        }
        __syncthreads();  // crow/P ready

        // ---- o rescale by this chunk's per-row ca ----
        float caA = crow[wm0 + (lane >> 2)];
        float caB = crow[wm0 + 8 + (lane >> 2)];
#pragma unroll
        for (int nt = 0; nt < 8; nt++) {
            o[nt][0] *= caA; o[nt][1] *= caA;
            o[nt][2] *= caB; o[nt][3] *= caB;
        }

        // ---- O += P V : A from P smem (validated A path), B from VT (validated B path) ----
#pragma unroll
        for (int kt = 0; kt < 8; kt++) {
            uint32_t pa[4], pb[4];
            ldsm4(pa, s0 + OFF_PH + ap_lane + (uint32_t)kt * 32u);
            ldsm4(pb, s0 + OFF_PL + ap_lane + (uint32_t)kt * 32u);
#pragma unroll
            for (int dp = 0; dp < 4; dp++) {
                uint32_t vh[4], vl[4];
                uint32_t voff = vb_lane + (uint32_t)dp * (16 * VRS) + (uint32_t)kt * 32u;
                ldsm4(vh, s0 + OFF_VH + voff);
                ldsm4(vl, s0 + OFF_VL + voff);
#pragma unroll
                for (int hf = 0; hf < 2; hf++) {
                    int nt = dp * 2 + hf;
                    mma16816(o[nt], pa, &vh[hf * 2]);
                    mma16816(o[nt], pa, &vl[hf * 2]);
                    mma16816(o[nt], pb, &vh[hf * 2]);
                }
            }
        }
        __syncthreads();  // all reads done before next chunk overwrites smem
    }

    // ---- normalize + store split bf16 ----
    float la = lrow[wm0 + (lane >> 2)];
    float lb = lrow[wm0 + 8 + (lane >> 2)];
    float ia = 1.0f / la, ib = 1.0f / lb;
    int ra = qt * 128 + wm0 + (lane >> 2);
    int rb = ra + 8;
#pragma unroll
    for (int nt = 0; nt < 8; nt++) {
        int col = h * 64 + nt * 8 + 2 * (lane & 3);
        if (ra < NTOK) {
            size_t p = (size_t)(b * NTOK + ra) * DM + col;
            uint32_t lo, hi = packsplit_hi(o[nt][0] * ia, o[nt][1] * ia, lo);
            *reinterpret_cast<uint32_t*>(yh + p) = hi;
            *reinterpret_cast<uint32_t*>(yl + p) = lo;
        }
        if (rb < NTOK) {
            size_t p = (size_t)(b * NTOK + rb) * DM + col;
            uint32_t lo, hi = packsplit_hi(o[nt][2] * ib, o[nt][3] * ib, lo);
            *reinterpret_cast<uint32_t*>(yh + p) = hi;
            *reinterpret_cast<uint32_t*>(yl + p) = lo;
        }
    }
}

// ---------------- HMMA (mma.sync bf16) split GEMM (round-4 validated) ----------------
template <int BN, int EPI>
__global__ void __launch_bounds__(256, 1)
hmma_gemm(const bf16* __restrict__ Ahi, const bf16* __restrict__ Alo, int lda,
          const bf16* __restrict__ Bhi, const bf16* __restrict__ Blo, int ldb,
          float* __restrict__ Cf, bf16* __restrict__ Chi, bf16* __restrict__ Clo, int ldc,
          const float* __restrict__ bias, const float* __restrict__ res,
          int M, int N, int NC, float alpha) {
    constexpr int WGN = (BN == 128) ? 4 : 2;
    constexpr int WGM = 8 / WGN;
    constexpr int WM  = 128 / WGM;
    constexpr int MT  = WM / 16;
    constexpr int RS  = 144;
    constexpr int ASZ = 128 * RS;
    constexpr int BSZ = BN * RS;
    constexpr int BUF = 2 * ASZ + 2 * BSZ;

    extern __shared__ __align__(16) char smem[];
    uint32_t s0 = s2u(smem);

    const int tid = threadIdx.x, lane = tid & 31, warp = tid >> 5;
    const int wm0 = (warp / WGN) * WM;
    const int wn0 = (warp % WGN) * 32;
    const int row0 = blockIdx.y * 128, col0 = blockIdx.x * BN;

    float acc[MT][4][4];
#pragma unroll
    for (int i = 0; i < MT; i++)
#pragma unroll
        for (int j = 0; j < 4; j++)
#pragma unroll
            for (int k = 0; k < 4; k++) acc[i][j][k] = 0.f;

    const uint32_t a_lane = (uint32_t)(wm0 + (lane & 15)) * RS + (uint32_t)(lane >> 4) * 16u;
    const uint32_t b_lane = (uint32_t)(wn0 + (lane & 7) + ((lane >> 4) << 3)) * RS +
                            (uint32_t)((lane >> 3) & 1) * 16u;

    auto load_chunk = [&](int ck, int bsel) {
        uint32_t base = s0 + bsel * BUF;
#pragma unroll
        for (int i = 0; i < 4; i++) {
            int idx = tid + i * 256;
            int r = idx >> 3, c = idx & 7;
            int gm = row0 + r;
            bool v = gm < M;
            const bf16* ph = v ? (Ahi + (size_t)gm * lda + (size_t)ck * 64 + c * 8) : Ahi;
            const bf16* pl = v ? (Alo + (size_t)gm * lda + (size_t)ck * 64 + c * 8) : Alo;
            uint32_t d = base + (uint32_t)r * RS + (uint32_t)c * 16u;
            cp16(d, ph, v);
            cp16(d + ASZ, pl, v);
        }
#pragma unroll
        for (int i = 0; i < BN / 32; i++) {
            int idx = tid + i * 256;
            int r = idx >> 3, c = idx & 7;
            int gn = col0 + r;
            bool v = gn < N;
            const bf16* ph = v ? (Bhi + (size_t)gn * ldb + (size_t)ck * 64 + c * 8) : Bhi;
            const bf16* pl = v ? (Blo + (size_t)gn * ldb + (size_t)ck * 64 + c * 8) : Blo;
            uint32_t d = base + 2 * ASZ + (uint32_t)r * RS + (uint32_t)c * 16u;
            cp16(d, ph, v);
            cp16(d + BSZ, pl, v);
        }
        cpcommit();
    };

    auto compute = [&](int bsel) {
        uint32_t base = s0 + bsel * BUF;
        uint32_t ah = base, al = base + ASZ, bh = base + 2 * ASZ, bl = base + 2 * ASZ + BSZ;
#pragma unroll
        for (int ks = 0; ks < 4; ks++) {
            uint32_t afh[MT][4], afl[MT][4];
#pragma unroll
            for (int mt = 0; mt < MT; mt++) {
                uint32_t off = a_lane + (uint32_t)mt * (16 * RS) + (uint32_t)ks * 32u;
                ldsm4(afh[mt], ah + off);
                ldsm4(afl[mt], al + off);
            }
            uint32_t bfh[2][4], bfl[2][4];
#pragma unroll
            for (int np = 0; np < 2; np++) {
                uint32_t off = b_lane + (uint32_t)np * (16 * RS) + (uint32_t)ks * 32u;
                ldsm4(bfh[np], bh + off);
                ldsm4(bfl[np], bl + off);
            }
#pragma unroll
            for (int mt = 0; mt < MT; mt++)
#pragma unroll
                for (int nt = 0; nt < 4; nt++) {
                    const uint32_t* Bh2 = &bfh[nt >> 1][(nt & 1) * 2];
                    const uint32_t* Bl2 = &bfl[nt >> 1][(nt & 1) * 2];
                    mma16816(acc[mt][nt], afh[mt], Bh2);
                    mma16816(acc[mt][nt], afh[mt], Bl2);
                    mma16816(acc[mt][nt], afl[mt], Bh2);
                }
        }
    };

    load_chunk(0, 0);
    for (int ck = 0; ck < NC; ck++) {
        if (ck + 1 < NC) { load_chunk(ck + 1, (ck + 1) & 1); cpwait1(); }
        else             { cpwait0(); }
        __syncthreads();
        compute(ck & 1);
        __syncthreads();
    }

#pragma unroll
    for (int mt = 0; mt < MT; mt++) {
#pragma unroll
        for (int nt = 0; nt < 4; nt++) {
            int r0 = row0 + wm0 + mt * 16 + (lane >> 2);
            int c0 = col0 + wn0 + nt * 8 + (lane & 3) * 2;
            float* a4 = acc[mt][nt];
            if (EPI == 0) {
#pragma unroll
                for (int h = 0; h < 2; h++) {
                    int gm = r0 + h * 8;
                    if (gm >= M) continue;
#pragma unroll
                    for (int q = 0; q < 2; q++) {
                        int gn = c0 + q;
                        if (gn >= N) continue;
                        float v = a4[h * 2 + q] * alpha;
                        if (bias) v += bias[gn];
                        if (res)  v += res[(size_t)gm * ldc + gn];
                        Cf[(size_t)gm * ldc + gn] = v;
                    }
                }
            } else {
#pragma unroll
                for (int h = 0; h < 2; h++) {
                    int gm = r0 + h * 8;
                    if (gm >= M) continue;
                    float v0 = a4[h * 2], v1 = a4[h * 2 + 1];
                    if (bias) { v0 += bias[c0]; v1 += bias[c0 + 1]; }
                    if (EPI == 2) { v0 = geluf(v0); v1 = geluf(v1); }
                    uint32_t lo, hi = packsplit_hi(v0, v1, lo);
                    *reinterpret_cast<uint32_t*>(Chi + (size_t)gm * ldc + c0) = hi;
                    *reinterpret_cast<uint32_t*>(Clo + (size_t)gm * ldc + c0) = lo;
                }
            }
        }
    }
}

// ---------------- host-side GEMM launcher ----------------
template <int BN, int EPI>
static void ggemm(const bf16* Ah, const bf16* Al, int lda,
                  const bf16* Bh, const bf16* Bl, int ldb,
                  float* Cf, bf16* Ch, bf16* Cl, int ldc,
                  const float* bias, const float* res,
                  int M, int N, int K, float alpha) {
    constexpr int RS = 144;
    constexpr int BUF = 2 * 128 * RS + 2 * BN * RS;
    int smem = 2 * BUF;
    cudaFuncSetAttribute(hmma_gemm<BN, EPI>, cudaFuncAttributeMaxDynamicSharedMemorySize, smem);
    dim3 grid((N + BN - 1) / BN, (M + 127) / 128, 1);
    hmma_gemm<BN, EPI><<<grid, 256, smem>>>(Ah, Al, lda, Bh, Bl, ldb, Cf, Ch, Cl, ldc,
                                            bias, res, M, N, K / 64, alpha);
}

extern "C" void kernel_launch(void* const* d_in, const int* in_sizes, int n_in,
                              void* d_out, int out_size) {
    const float* x       = (const float*)d_in[0];
    const float* conv_w  = (const float*)d_in[1];
    const float* conv_b  = (const float*)d_in[2];
    const float* cls_tok = (const float*)d_in[3];
    const float* pos_emb = (const float*)d_in[4];
    const float* ln1_g   = (const float*)d_in[5];
    const float* ln1_b   = (const float*)d_in[6];
    const float* qkv_w   = (const float*)d_in[7];
    const float* qkv_b   = (const float*)d_in[8];
    const float* proj_w  = (const float*)d_in[9];
    const float* proj_b  = (const float*)d_in[10];
    const float* ln2_g   = (const float*)d_in[11];
    const float* ln2_b   = (const float*)d_in[12];
    const float* mlp_w1  = (const float*)d_in[13];
    const float* mlp_b1  = (const float*)d_in[14];
    const float* mlp_w2  = (const float*)d_in[15];
    const float* mlp_b2  = (const float*)d_in[16];
    const float* lnf_g   = (const float*)d_in[17];
    const float* lnf_b   = (const float*)d_in[18];
    float* out = (float*)d_out;

    bf16 *phi, *plo, *cwhi, *cwlo, *whi, *wlo, *yhi, *ylo, *qhi, *qlo, *mhi, *mlo,
         *vthi, *vtlo;
    float *ph, *ptmp;
    cudaGetSymbolAddress((void**)&phi, g_phi);
    cudaGetSymbolAddress((void**)&plo, g_plo);
    cudaGetSymbolAddress((void**)&cwhi, g_cwhi);
    cudaGetSymbolAddress((void**)&cwlo, g_cwlo);
    cudaGetSymbolAddress((void**)&whi, g_whi);
    cudaGetSymbolAddress((void**)&wlo, g_wlo);
    cudaGetSymbolAddress((void**)&ph, g_h);
    cudaGetSymbolAddress((void**)&ptmp, g_ptmp);
    cudaGetSymbolAddress((void**)&yhi, g_yhi);
    cudaGetSymbolAddress((void**)&ylo, g_ylo);
    cudaGetSymbolAddress((void**)&qhi, g_qhi);
    cudaGetSymbolAddress((void**)&qlo, g_qlo);
    cudaGetSymbolAddress((void**)&mhi, g_mhi);
    cudaGetSymbolAddress((void**)&mlo, g_mlo);
    cudaGetSymbolAddress((void**)&vthi, g_vthi);
    cudaGetSymbolAddress((void**)&vtlo, g_vtlo);

    dim3 tb(32, 8);

    // ---- weight prep ----
    split_kernel<<<(DM * DM + 255) / 256, 256>>>(conv_w, cwhi, cwlo, DM * DM);
    for (int l = 0; l < LAYERS; l++) {
        long long wo = (long long)l * LW;
        wt_trans<<<dim3(2304 / 32, 768 / 32), tb>>>(qkv_w + (size_t)l * DM * 3 * DM,
                                                    whi + wo, wlo + wo, DM, 3 * DM);
        wt_trans<<<dim3(768 / 32, 768 / 32), tb>>>(proj_w + (size_t)l * DM * DM,
                                                   whi + wo + 1769472, wlo + wo + 1769472, DM, DM);
        wt_trans<<<dim3(3072 / 32, 768 / 32), tb>>>(mlp_w1 + (size_t)l * DM * 4 * DM,
                                                    whi + wo + 2359296, wlo + wo + 2359296, DM, 4 * DM);
        wt_trans<<<dim3(768 / 32, 3072 / 32), tb>>>(mlp_w2 + (size_t)l * 4 * DM * DM,
                                                    whi + wo + 4718592, wlo + wo + 4718592, 4 * DM, DM);
    }

    // ---- patch embed ----
    im2col_split<<<(MPATCH * DM + 255) / 256, 256>>>(x, phi, plo);
    ggemm<128, 0>(phi, plo, DM, cwhi, cwlo, DM, ptmp, nullptr, nullptr, DM,
                  conv_b, nullptr, MPATCH, DM, DM, 1.0f);
    assemble_kernel<<<(MTOK * DM + 255) / 256, 256>>>(ptmp, cls_tok, pos_emb, ph);

    cudaFuncSetAttribute(fused_attn, cudaFuncAttributeMaxDynamicSharedMemorySize, FA_SMEM);

    for (int l = 0; l < LAYERS; l++) {
        long long wo = (long long)l * LW;
        const bf16* qwT_h = whi + wo;            const bf16* qwT_l = wlo + wo;
        const bf16* pwT_h = whi + wo + 1769472;  const bf16* pwT_l = wlo + wo + 1769472;
        const bf16* w1T_h = whi + wo + 2359296;  const bf16* w1T_l = wlo + wo + 2359296;
        const bf16* w2T_h = whi + wo + 4718592;  const bf16* w2T_l = wlo + wo + 4718592;
        const float* l1g = ln1_g + (size_t)l * DM;
        const float* l1b = ln1_b + (size_t)l * DM;
        const float* qb  = qkv_b + (size_t)l * 3 * DM;
        const float* pb  = proj_b + (size_t)l * DM;
        const float* l2g = ln2_g + (size_t)l * DM;
        const float* l2b = ln2_b + (size_t)l * DM;
        const float* b1  = mlp_b1 + (size_t)l * 4 * DM;
        const float* b2  = mlp_b2 + (size_t)l * DM;

        // LN1 -> split y
        ln_split<<<MTOK, 256>>>(ph, l1g, l1b, yhi, ylo);
        // QKV
        ggemm<128, 1>(yhi, ylo, DM, qwT_h, qwT_l, DM, nullptr, qhi, qlo, 3 * DM,
                      qb, nullptr, MTOK, 3 * DM, DM, 1.0f);
        // V transpose per head (validated)
        {
            size_t n = (size_t)BATCH * HEADS * 64 * SPAD;
            vt_split<<<(unsigned)((n + 255) / 256), 256>>>(qhi, qlo, vthi, vtlo);
        }
        // fused attention -> y (split), [B,N,H,dh] == [B,N,D]
        fused_attn<<<dim3(NCHUNK, BATCH * HEADS), 256, FA_SMEM>>>(qhi, qlo, vthi, vtlo,
                                                                  yhi, ylo);
        // proj + bias + residual
        ggemm<128, 0>(yhi, ylo, DM, pwT_h, pwT_l, DM, ph, nullptr, nullptr, DM,
                      pb, ph, MTOK, DM, DM, 1.0f);
        // LN2 -> split y
        ln_split<<<MTOK, 256>>>(ph, l2g, l2b, yhi, ylo);
        // MLP1 + gelu
        ggemm<128, 2>(yhi, ylo, DM, w1T_h, w1T_l, DM, nullptr, mhi, mlo, 4 * DM,
                      b1, nullptr, MTOK, 4 * DM, DM, 1.0f);
        // MLP2 + bias + residual
        ggemm<128, 0>(mhi, mlo, 4 * DM, w2T_h, w2T_l, 4 * DM, ph, nullptr, nullptr, DM,
                      b2, ph, MTOK, DM, 4 * DM, 1.0f);
    }

    // final LN on CLS rows -> out [8,768]
    ln_kernel<<<BATCH, 256>>>(ph, lnf_g, lnf_b, out, (long long)NTOK * DM, DM);
}

// round 8
// speedup vs baseline: 2.4967x; 1.0488x over previous
#include <cuda_runtime.h>
#include <cuda_bf16.h>
#include <math.h>
#include <stdint.h>

using bf16 = __nv_bfloat16;

// ---------------- problem constants ----------------
static constexpr int BATCH  = 8;
static constexpr int DM     = 768;
static constexpr int HEADS  = 12;
static constexpr int LAYERS = 12;
static constexpr int NTOK   = 785;
static constexpr int NPATCH = 784;
static constexpr int MTOK   = BATCH * NTOK;    // 6280
static constexpr int MPATCH = BATCH * NPATCH;  // 6272
static constexpr int IMG    = 448;
static constexpr int PSZ    = 16;
static constexpr int GRID28 = 28;
static constexpr int SPAD   = 896;             // padded token stride for vT (7*128)
static constexpr long long LW = 7077888LL;     // per-layer transposed-weight stride

// ---------------- device scratch ----------------
__device__ bf16  g_phi[(size_t)MPATCH * DM];
__device__ bf16  g_plo[(size_t)MPATCH * DM];
__device__ bf16  g_cwhi[DM * DM];
__device__ bf16  g_cwlo[DM * DM];
__device__ bf16  g_whi[(size_t)LAYERS * LW];
__device__ bf16  g_wlo[(size_t)LAYERS * LW];
__device__ float g_h[(size_t)MTOK * DM];
__device__ float g_ptmp[(size_t)MPATCH * DM];   // fp32 patch temp
__device__ bf16  g_yhi[(size_t)MTOK * DM];
__device__ bf16  g_ylo[(size_t)MTOK * DM];
__device__ bf16  g_qhi[(size_t)MTOK * 3 * DM];
__device__ bf16  g_qlo[(size_t)MTOK * 3 * DM];
__device__ bf16  g_mhi[(size_t)MTOK * 4 * DM];
__device__ bf16  g_mlo[(size_t)MTOK * 4 * DM];
__device__ bf16  g_vthi[(size_t)BATCH * HEADS * 64 * SPAD];
__device__ bf16  g_vtlo[(size_t)BATCH * HEADS * 64 * SPAD];

// ---------------- small helpers ----------------
__device__ __forceinline__ void split2(float v, bf16& h, bf16& l) {
    h = __float2bfloat16(v);
    l = __float2bfloat16(v - __bfloat162float(h));
}
__device__ __forceinline__ float geluf(float v) {
    return 0.5f * v * (1.0f + erff(v * 0.70710678118654752f));
}
__device__ __forceinline__ float warpSum(float v) {
#pragma unroll
    for (int o = 16; o > 0; o >>= 1) v += __shfl_xor_sync(0xffffffffu, v, o);
    return v;
}
__device__ __forceinline__ float blockSum256(float v, float* sh) {
    int lane = threadIdx.x & 31, w = threadIdx.x >> 5;
    v = warpSum(v);
    if (lane == 0) sh[w] = v;
    __syncthreads();
    float r = (threadIdx.x < 8) ? sh[threadIdx.x] : 0.f;
    if (w == 0) { r = warpSum(r); if (lane == 0) sh[0] = r; }
    __syncthreads();
    r = sh[0];
    __syncthreads();
    return r;
}

// ---------------- PTX wrappers (plain sm_103-legal only) ----------------
__device__ __forceinline__ uint32_t s2u(const void* p) {
    uint32_t a;
    asm("{ .reg .u64 t; cvta.to.shared.u64 t, %1; cvt.u32.u64 %0, t; }" : "=r"(a) : "l"(p));
    return a;
}
__device__ __forceinline__ void cp16(uint32_t d, const void* s, bool pred) {
    int sz = pred ? 16 : 0;
    asm volatile("cp.async.cg.shared.global [%0], [%1], 16, %2;" :: "r"(d), "l"(s), "r"(sz));
}
__device__ __forceinline__ void cpcommit() { asm volatile("cp.async.commit_group;" ::: "memory"); }
__device__ __forceinline__ void cpwait0()  { asm volatile("cp.async.wait_group 0;" ::: "memory"); }
__device__ __forceinline__ void cpwait1()  { asm volatile("cp.async.wait_group 1;" ::: "memory"); }
__device__ __forceinline__ void ldsm4(uint32_t* r, uint32_t addr) {
    asm volatile("ldmatrix.sync.aligned.m8n8.x4.shared.b16 {%0,%1,%2,%3}, [%4];"
                 : "=r"(r[0]), "=r"(r[1]), "=r"(r[2]), "=r"(r[3]) : "r"(addr));
}
__device__ __forceinline__ void mma16816(float* c, const uint32_t* a, const uint32_t* b) {
    asm volatile(
        "mma.sync.aligned.m16n8k16.row.col.f32.bf16.bf16.f32 "
        "{%0,%1,%2,%3}, {%4,%5,%6,%7}, {%8,%9}, {%0,%1,%2,%3};"
        : "+f"(c[0]), "+f"(c[1]), "+f"(c[2]), "+f"(c[3])
        : "r"(a[0]), "r"(a[1]), "r"(a[2]), "r"(a[3]), "r"(b[0]), "r"(b[1]));
}
__device__ __forceinline__ uint32_t packsplit_hi(float a, float b, uint32_t& lo) {
    bf16 ah, al, bh, bl;
    split2(a, ah, al);
    split2(b, bh, bl);
    __nv_bfloat162 h2; h2.x = ah; h2.y = bh;
    __nv_bfloat162 l2; l2.x = al; l2.y = bl;
    lo = *reinterpret_cast<uint32_t*>(&l2);
    return *reinterpret_cast<uint32_t*>(&h2);
}

// ---------------- elementwise / prep kernels ----------------
__global__ void im2col_split(const float* __restrict__ x, bf16* __restrict__ Ph,
                             bf16* __restrict__ Pl) {
    int idx = blockIdx.x * blockDim.x + threadIdx.x;
    if (idx >= MPATCH * DM) return;
    int k = idx % DM, m = idx / DM;
    int b = m / NPATCH, t = m % NPATCH;
    int py = t / GRID28, px = t % GRID28;
    int c = k >> 8, rem = k & 255, i = rem >> 4, j = rem & 15;
    size_t src = (((size_t)(b * 3 + c) * IMG) + (size_t)(py * PSZ + i)) * IMG + (px * PSZ + j);
    bf16 h, l;
    split2(x[src], h, l);
    Ph[idx] = h; Pl[idx] = l;
}

__global__ void split_kernel(const float* __restrict__ W, bf16* __restrict__ Oh,
                             bf16* __restrict__ Ol, int n) {
    int idx = blockIdx.x * blockDim.x + threadIdx.x;
    if (idx >= n) return;
    bf16 h, l;
    split2(W[idx], h, l);
    Oh[idx] = h; Ol[idx] = l;
}

// W[K,N] row-major -> out[n*K + k] (transpose + split), tiled
__global__ void wt_trans(const float* __restrict__ W, bf16* __restrict__ Oh,
                         bf16* __restrict__ Ol, int K, int N) {
    __shared__ float tile[32][33];
    int kb = blockIdx.y * 32, nb = blockIdx.x * 32;
    int tx = threadIdx.x, ty = threadIdx.y;  // 32 x 8
#pragma unroll
    for (int i = 0; i < 32; i += 8) {
        int k = kb + ty + i, n = nb + tx;
        tile[ty + i][tx] = (k < K && n < N) ? W[(size_t)k * N + n] : 0.f;
    }
    __syncthreads();
#pragma unroll
    for (int i = 0; i < 32; i += 8) {
        int n = nb + ty + i, k = kb + tx;
        if (n < N && k < K) {
            bf16 h, l;
            split2(tile[tx][ty + i], h, l);
            Oh[(size_t)n * K + k] = h;
            Ol[(size_t)n * K + k] = l;
        }
    }
}

__global__ void assemble_kernel(const float* __restrict__ tok, const float* __restrict__ cls,
                                const float* __restrict__ pos, float* __restrict__ H) {
    int idx = blockIdx.x * blockDim.x + threadIdx.x;
    if (idx >= MTOK * DM) return;
    int d = idx % DM;
    int r = idx / DM;
    int n = r % NTOK, b = r / NTOK;
    float v;
    if (n == 0) v = cls[d] + pos[d];
    else        v = tok[((size_t)b * NPATCH + (n - 1)) * DM + d] + pos[(size_t)n * DM + d];
    H[idx] = v;
}

__global__ void ln_kernel(const float* __restrict__ X, const float* __restrict__ g,
                          const float* __restrict__ bb, float* __restrict__ Y,
                          long long inStride, long long outStride) {
    const float* x = X + (long long)blockIdx.x * inStride;
    float* y = Y + (long long)blockIdx.x * outStride;
    int t = threadIdx.x;
    __shared__ float sh[8];
    float v0 = x[t], v1 = x[t + 256], v2 = x[t + 512];
    float mu = blockSum256(v0 + v1 + v2, sh) * (1.0f / 768.0f);
    float d0 = v0 - mu, d1 = v1 - mu, d2 = v2 - mu;
    float var = blockSum256(d0 * d0 + d1 * d1 + d2 * d2, sh) * (1.0f / 768.0f);
    float rs = rsqrtf(var + 1e-5f);
    y[t]       = d0 * rs * g[t]       + bb[t];
    y[t + 256] = d1 * rs * g[t + 256] + bb[t + 256];
    y[t + 512] = d2 * rs * g[t + 512] + bb[t + 512];
}

__global__ void ln_split(const float* __restrict__ X, const float* __restrict__ g,
                         const float* __restrict__ bb, bf16* __restrict__ Yh,
                         bf16* __restrict__ Yl) {
    const float* x = X + (size_t)blockIdx.x * DM;
    bf16* yh = Yh + (size_t)blockIdx.x * DM;
    bf16* yl = Yl + (size_t)blockIdx.x * DM;
    int t = threadIdx.x;
    __shared__ float sh[8];
    float v0 = x[t], v1 = x[t + 256], v2 = x[t + 512];
    float mu = blockSum256(v0 + v1 + v2, sh) * (1.0f / 768.0f);
    float d0 = v0 - mu, d1 = v1 - mu, d2 = v2 - mu;
    float var = blockSum256(d0 * d0 + d1 * d1 + d2 * d2, sh) * (1.0f / 768.0f);
    float rs = rsqrtf(var + 1e-5f);
    float o0 = d0 * rs * g[t] + bb[t];
    float o1 = d1 * rs * g[t + 256] + bb[t + 256];
    float o2 = d2 * rs * g[t + 512] + bb[t + 512];
    bf16 h, l;
    split2(o0, h, l); yh[t] = h;       yl[t] = l;
    split2(o1, h, l); yh[t + 256] = h; yl[t + 256] = l;
    split2(o2, h, l); yh[t + 512] = h; yl[t + 512] = l;
}

// vT[z][d][t] = qkv[b*785+t][1536 + h*64 + d], zero tail in t  (validated round 4)
__global__ void vt_split(const bf16* __restrict__ Qh, const bf16* __restrict__ Ql,
                         bf16* __restrict__ Vh, bf16* __restrict__ Vl) {
    size_t idx = (size_t)blockIdx.x * blockDim.x + threadIdx.x;
    if (idx >= (size_t)BATCH * HEADS * 64 * SPAD) return;
    int t = (int)(idx % SPAD);
    int d = (int)((idx / SPAD) % 64);
    int z = (int)(idx / ((size_t)SPAD * 64));
    int b = z / HEADS, h = z % HEADS;
    bf16 vh = __float2bfloat16(0.f), vl = vh;
    if (t < NTOK) {
        size_t src = ((size_t)(b * NTOK + t)) * (3 * DM) + 2 * DM + h * 64 + d;
        vh = Qh[src]; vl = Ql[src];
    }
    Vh[idx] = vh; Vl[idx] = vl;
}

// ---------------- fused flash attention v4 (double-buffered K/V) ----------------
// One block = 128 query rows of one (b,h). 8 warps x 16 rows.
// S is staged as split-bf16 hi/lo (same region as P); softmax is linear and
// IN-PLACE (each thread owns a disjoint 128B slice per plane). K/V chunks are
// double-buffered with the same prefetch pattern as the validated dense GEMM.
static constexpr int ARS    = 144;              // K/Q tile row stride  [128 x 64]
static constexpr int KTILE  = 128 * ARS;        // 18432
static constexpr int VRS    = 272;              // VT tile row stride   [64 x 128]
static constexpr int VTILE  = 64 * VRS;         // 17408
static constexpr int KVBUF  = 2 * KTILE + 2 * VTILE;   // 71680
static constexpr int PRS2   = 272;              // S/P row stride bytes (128 cols x 2B + pad)
static constexpr int SPTILE = 128 * PRS2;       // 34816
static constexpr int OFF_SPH = 2 * KVBUF;              // 143360
static constexpr int OFF_SPL = OFF_SPH + SPTILE;       // 178176
static constexpr int OFF_M  = OFF_SPL + SPTILE;        // 212992
static constexpr int OFF_L  = OFF_M + 512;             // 213504
static constexpr int OFF_CA = OFF_L + 512;             // 214016
static constexpr int OFF_T  = OFF_CA + 512;            // 214528
static constexpr int FA_SMEM = OFF_T + 1024;           // 215552
static constexpr int NCHUNK = 7;

__global__ void __launch_bounds__(256, 1)
fused_attn(const bf16* __restrict__ qkvh, const bf16* __restrict__ qkvl,
           const bf16* __restrict__ vth, const bf16* __restrict__ vtl,
           bf16* __restrict__ yh, bf16* __restrict__ yl) {
    extern __shared__ __align__(16) char smem[];
    uint32_t s0 = s2u(smem);
    const int tid = threadIdx.x, lane = tid & 31, warp = tid >> 5;
    const int qt = blockIdx.x;                 // 0..6
    const int z = blockIdx.y;                  // 0..95
    const int b = z / HEADS, h = z % HEADS;
    const float SC = 0.125f;

    const int wm0 = warp * 16;
    const uint32_t a_lane  = (uint32_t)(wm0 + (lane & 15)) * ARS + (uint32_t)(lane >> 4) * 16u;
    const uint32_t b_lane  = (uint32_t)((lane & 7) + ((lane >> 4) << 3)) * ARS +
                             (uint32_t)((lane >> 3) & 1) * 16u;
    const uint32_t vb_lane = (uint32_t)((lane & 7) + ((lane >> 4) << 3)) * VRS +
                             (uint32_t)((lane >> 3) & 1) * 16u;
    const uint32_t ap_lane = (uint32_t)(wm0 + (lane & 15)) * PRS2 + (uint32_t)(lane >> 4) * 16u;

    float* mrow = reinterpret_cast<float*>(smem + OFF_M);
    float* lrow = reinterpret_cast<float*>(smem + OFF_L);
    float* crow = reinterpret_cast<float*>(smem + OFF_CA);
    float* tred = reinterpret_cast<float*>(smem + OFF_T);

    // load a [128x64] hi/lo pair from qkv into smem (identical pattern to gemm loader)
    auto load_qk = [&](int rowbase, int colbase, uint32_t dsth, uint32_t dstl) {
#pragma unroll
        for (int i = 0; i < 4; i++) {
            int idx = tid + i * 256;
            int r = idx >> 3, g = idx & 7;
            bool v = (rowbase + r) < NTOK;
            size_t off = ((size_t)(b * NTOK + rowbase + r)) * (3 * DM) + colbase + g * 8;
            const bf16* sh2 = v ? (qkvh + off) : qkvh;
            const bf16* sl2 = v ? (qkvl + off) : qkvl;
            uint32_t d = (uint32_t)r * ARS + (uint32_t)g * 16u;
            cp16(dsth + d, sh2, v);
            cp16(dstl + d, sl2, v);
        }
    };
    auto load_vt = [&](int c, uint32_t dsth, uint32_t dstl) {
        const bf16* bh2 = vth + (size_t)z * 64 * SPAD + (size_t)c * 128;
        const bf16* bl2 = vtl + (size_t)z * 64 * SPAD + (size_t)c * 128;
#pragma unroll
        for (int i = 0; i < 4; i++) {
            int idx = tid + i * 256;
            int r = idx >> 4, g = idx & 15;
            size_t off = (size_t)r * SPAD + g * 8;
            uint32_t d = (uint32_t)r * VRS + (uint32_t)g * 16u;
            cp16(dsth + d, bh2 + off, true);
            cp16(dstl + d, bl2 + off, true);
        }
    };
    auto load_chunk = [&](int c, int bsel) {
        uint32_t base = s0 + bsel * KVBUF;
        load_qk(c * 128, DM + h * 64, base, base + KTILE);           // K hi/lo
        load_vt(c, base + 2 * KTILE, base + 2 * KTILE + VTILE);      // VT hi/lo
        cpcommit();
    };

    // ---- stage Q (in SP region), pull to registers ----
    load_qk(qt * 128, h * 64, s0 + OFF_SPH, s0 + OFF_SPH + KTILE);
    cpcommit();
    cpwait0();
    __syncthreads();
    uint32_t aQh[4][4], aQl[4][4];
#pragma unroll
    for (int ks = 0; ks < 4; ks++) {
        ldsm4(aQh[ks], s0 + OFF_SPH + a_lane + ks * 32);
        ldsm4(aQl[ks], s0 + OFF_SPH + KTILE + a_lane + ks * 32);
    }
    if (tid < 128) { mrow[tid] = -1e30f; lrow[tid] = 0.f; }
    __syncthreads();   // Q consumed; SP region reusable; m/l ready

    float o[8][4];
#pragma unroll
    for (int i = 0; i < 8; i++)
#pragma unroll
        for (int j = 0; j < 4; j++) o[i][j] = 0.f;

    load_chunk(0, 0);
    for (int c = 0; c < NCHUNK; c++) {
        if (c + 1 < NCHUNK) { load_chunk(c + 1, (c + 1) & 1); cpwait1(); }
        else                { cpwait0(); }
        __syncthreads();
        uint32_t kvb = s0 + (c & 1) * KVBUF;
        uint32_t Kh = kvb, Kl = kvb + KTILE;
        uint32_t Vh = kvb + 2 * KTILE, Vl = kvb + 2 * KTILE + VTILE;

        // ---- S = Q K^T (3-term split) ----
        float s[16][4];
#pragma unroll
        for (int j = 0; j < 16; j++)
#pragma unroll
            for (int q = 0; q < 4; q++) s[j][q] = 0.f;
#pragma unroll
        for (int ks = 0; ks < 4; ks++) {
#pragma unroll
            for (int jp = 0; jp < 8; jp++) {
                uint32_t kh[4], kl[4];
                uint32_t koff = b_lane + (uint32_t)jp * (16 * ARS) + (uint32_t)ks * 32u;
                ldsm4(kh, Kh + koff);
                ldsm4(kl, Kl + koff);
#pragma unroll
                for (int hf = 0; hf < 2; hf++) {
                    int j = jp * 2 + hf;
                    mma16816(s[j], aQh[ks], &kh[hf * 2]);
                    mma16816(s[j], aQh[ks], &kl[hf * 2]);
                    mma16816(s[j], aQl[ks], &kh[hf * 2]);
                }
            }
        }

        // ---- dump S as split bf16 hi/lo (validated EPI=1 store formula) ----
        {
            char* smp = smem;
            int r0 = wm0 + (lane >> 2);
            int c0 = 2 * (lane & 3);
#pragma unroll
            for (int j = 0; j < 16; j++) {
                int cc = j * 8 + c0;
                uint32_t loA, hiA = packsplit_hi(s[j][0], s[j][1], loA);
                uint32_t loB, hiB = packsplit_hi(s[j][2], s[j][3], loB);
                *(uint32_t*)(smp + OFF_SPH + (uint32_t)r0 * PRS2 + cc * 2) = hiA;
                *(uint32_t*)(smp + OFF_SPL + (uint32_t)r0 * PRS2 + cc * 2) = loA;
                *(uint32_t*)(smp + OFF_SPH + (uint32_t)(r0 + 8) * PRS2 + cc * 2) = hiB;
                *(uint32_t*)(smp + OFF_SPL + (uint32_t)(r0 + 8) * PRS2 + cc * 2) = loB;
            }
        }
        __syncthreads();

        // ---- linear softmax IN-PLACE: row r = tid>>1, half = tid&1 (64 cols) ----
        const int r = tid >> 1, half = tid & 1;
        char* smp = smem;
        const uint32_t rowoff = (uint32_t)r * PRS2 + (uint32_t)half * 128u;
        const int colbase = c * 128 + half * 64;
        const int nvalid0 = NTOK - colbase;
        const int nvalid = nvalid0 < 0 ? 0 : (nvalid0 > 64 ? 64 : nvalid0);

        float chmax = -1e30f;
#pragma unroll 8
        for (int k = 0; k < 64; k += 2) {
            uint32_t hi = *(uint32_t*)(smp + OFF_SPH + rowoff + k * 2);
            uint32_t lo = *(uint32_t*)(smp + OFF_SPL + rowoff + k * 2);
            __nv_bfloat162 h2 = *reinterpret_cast<__nv_bfloat162*>(&hi);
            __nv_bfloat162 l2 = *reinterpret_cast<__nv_bfloat162*>(&lo);
            float v0 = __bfloat162float(h2.x) + __bfloat162float(l2.x);
            float v1 = __bfloat162float(h2.y) + __bfloat162float(l2.y);
            if (k < nvalid)     chmax = fmaxf(chmax, v0);
            if (k + 1 < nvalid) chmax = fmaxf(chmax, v1);
        }
        tred[tid] = chmax;
        __syncthreads();
        float m_old = mrow[r];
        float rmax = fmaxf(tred[2 * r], tred[2 * r + 1]);
        float m_new = fmaxf(m_old, rmax);
        float ca = __expf(SC * (m_old - m_new));
        __syncthreads();  // tred free for reuse

        float esum = 0.f;
#pragma unroll 8
        for (int k = 0; k < 64; k += 2) {
            uint32_t hi = *(uint32_t*)(smp + OFF_SPH + rowoff + k * 2);
            uint32_t lo = *(uint32_t*)(smp + OFF_SPL + rowoff + k * 2);
            __nv_bfloat162 h2 = *reinterpret_cast<__nv_bfloat162*>(&hi);
            __nv_bfloat162 l2 = *reinterpret_cast<__nv_bfloat162*>(&lo);
            float v0 = __bfloat162float(h2.x) + __bfloat162float(l2.x);
            float v1 = __bfloat162float(h2.y) + __bfloat162float(l2.y);
            float e0 = (k < nvalid)     ? __expf(SC * (v0 - m_new)) : 0.f;
            float e1 = (k + 1 < nvalid) ? __expf(SC * (v1 - m_new)) : 0.f;
            esum += e0 + e1;
            uint32_t plo, phi = packsplit_hi(e0, e1, plo);
            *(uint32_t*)(smp + OFF_SPH + rowoff + k * 2) = phi;
            *(uint32_t*)(smp + OFF_SPL + rowoff + k * 2) = plo;
        }
        tred[tid] = esum;
        __syncthreads();
        if (half == 0) {
            lrow[r] = lrow[r] * ca + tred[2 * r] + tred[2 * r + 1];
            mrow[r] = m_new;
            crow[r] = ca;
        }
        __syncthreads();  // crow/P ready

        // ---- o rescale by this chunk's per-row ca ----
        float caA = crow[wm0 + (lane >> 2)];
        float caB = crow[wm0 + 8 + (lane >> 2)];
#pragma unroll
        for (int nt = 0; nt < 8; nt++) {
            o[nt][0] *= caA; o[nt][1] *= caA;
            o[nt][2] *= caB; o[nt][3] *= caB;
        }

        // ---- O += P V : A from P smem (validated A path), B from VT (validated B path) ----
#pragma unroll
        for (int kt = 0; kt < 8; kt++) {
            uint32_t pa[4], pb[4];
            ldsm4(pa, s0 + OFF_SPH + ap_lane + (uint32_t)kt * 32u);
            ldsm4(pb, s0 + OFF_SPL + ap_lane + (uint32_t)kt * 32u);
#pragma unroll
            for (int dp = 0; dp < 4; dp++) {
                uint32_t vh[4], vl[4];
                uint32_t voff = vb_lane + (uint32_t)dp * (16 * VRS) + (uint32_t)kt * 32u;
                ldsm4(vh, Vh + voff);
                ldsm4(vl, Vl + voff);
#pragma unroll
                for (int hf = 0; hf < 2; hf++) {
                    int nt = dp * 2 + hf;
                    mma16816(o[nt], pa, &vh[hf * 2]);
                    mma16816(o[nt], pa, &vl[hf * 2]);
                    mma16816(o[nt], pb, &vh[hf * 2]);
                }
            }
        }
        __syncthreads();  // all reads done before next chunk overwrites smem
    }

    // ---- normalize + store split bf16 ----
    float la = lrow[wm0 + (lane >> 2)];
    float lb = lrow[wm0 + 8 + (lane >> 2)];
    float ia = 1.0f / la, ib = 1.0f / lb;
    int ra = qt * 128 + wm0 + (lane >> 2);
    int rb = ra + 8;
#pragma unroll
    for (int nt = 0; nt < 8; nt++) {
        int col = h * 64 + nt * 8 + 2 * (lane & 3);
        if (ra < NTOK) {
            size_t p = (size_t)(b * NTOK + ra) * DM + col;
            uint32_t lo, hi = packsplit_hi(o[nt][0] * ia, o[nt][1] * ia, lo);
            *reinterpret_cast<uint32_t*>(yh + p) = hi;
            *reinterpret_cast<uint32_t*>(yl + p) = lo;
        }
        if (rb < NTOK) {
            size_t p = (size_t)(b * NTOK + rb) * DM + col;
            uint32_t lo, hi = packsplit_hi(o[nt][2] * ib, o[nt][3] * ib, lo);
            *reinterpret_cast<uint32_t*>(yh + p) = hi;
            *reinterpret_cast<uint32_t*>(yl + p) = lo;
        }
    }
}

// ---------------- HMMA (mma.sync bf16) split GEMM (round-4 validated) ----------------
template <int BN, int EPI>
__global__ void __launch_bounds__(256, 1)
hmma_gemm(const bf16* __restrict__ Ahi, const bf16* __restrict__ Alo, int lda,
          const bf16* __restrict__ Bhi, const bf16* __restrict__ Blo, int ldb,
          float* __restrict__ Cf, bf16* __restrict__ Chi, bf16* __restrict__ Clo, int ldc,
          const float* __restrict__ bias, const float* __restrict__ res,
          int M, int N, int NC, float alpha) {
    constexpr int WGN = (BN == 128) ? 4 : 2;
    constexpr int WGM = 8 / WGN;
    constexpr int WM  = 128 / WGM;
    constexpr int MT  = WM / 16;
    constexpr int RS  = 144;
    constexpr int ASZ = 128 * RS;
    constexpr int BSZ = BN * RS;
    constexpr int BUF = 2 * ASZ + 2 * BSZ;

    extern __shared__ __align__(16) char smem[];
    uint32_t s0 = s2u(smem);

    const int tid = threadIdx.x, lane = tid & 31, warp = tid >> 5;
    const int wm0 = (warp / WGN) * WM;
    const int wn0 = (warp % WGN) * 32;
    const int row0 = blockIdx.y * 128, col0 = blockIdx.x * BN;

    float acc[MT][4][4];
#pragma unroll
    for (int i = 0; i < MT; i++)
#pragma unroll
        for (int j = 0; j < 4; j++)
#pragma unroll
            for (int k = 0; k < 4; k++) acc[i][j][k] = 0.f;

    const uint32_t a_lane = (uint32_t)(wm0 + (lane & 15)) * RS + (uint32_t)(lane >> 4) * 16u;
    const uint32_t b_lane = (uint32_t)(wn0 + (lane & 7) + ((lane >> 4) << 3)) * RS +
                            (uint32_t)((lane >> 3) & 1) * 16u;

    auto load_chunk = [&](int ck, int bsel) {
        uint32_t base = s0 + bsel * BUF;
#pragma unroll
        for (int i = 0; i < 4; i++) {
            int idx = tid + i * 256;
            int r = idx >> 3, c = idx & 7;
            int gm = row0 + r;
            bool v = gm < M;
            const bf16* ph = v ? (Ahi + (size_t)gm * lda + (size_t)ck * 64 + c * 8) : Ahi;
            const bf16* pl = v ? (Alo + (size_t)gm * lda + (size_t)ck * 64 + c * 8) : Alo;
            uint32_t d = base + (uint32_t)r * RS + (uint32_t)c * 16u;
            cp16(d, ph, v);
            cp16(d + ASZ, pl, v);
        }
#pragma unroll
        for (int i = 0; i < BN / 32; i++) {
            int idx = tid + i * 256;
            int r = idx >> 3, c = idx & 7;
            int gn = col0 + r;
            bool v = gn < N;
            const bf16* ph = v ? (Bhi + (size_t)gn * ldb + (size_t)ck * 64 + c * 8) : Bhi;
            const bf16* pl = v ? (Blo + (size_t)gn * ldb + (size_t)ck * 64 + c * 8) : Blo;
            uint32_t d = base + 2 * ASZ + (uint32_t)r * RS + (uint32_t)c * 16u;
            cp16(d, ph, v);
            cp16(d + BSZ, pl, v);
        }
        cpcommit();
    };

    auto compute = [&](int bsel) {
        uint32_t base = s0 + bsel * BUF;
        uint32_t ah = base, al = base + ASZ, bh = base + 2 * ASZ, bl = base + 2 * ASZ + BSZ;
#pragma unroll
        for (int ks = 0; ks < 4; ks++) {
            uint32_t afh[MT][4], afl[MT][4];
#pragma unroll
            for (int mt = 0; mt < MT; mt++) {
                uint32_t off = a_lane + (uint32_t)mt * (16 * RS) + (uint32_t)ks * 32u;
                ldsm4(afh[mt], ah + off);
                ldsm4(afl[mt], al + off);
            }
            uint32_t bfh[2][4], bfl[2][4];
#pragma unroll
            for (int np = 0; np < 2; np++) {
                uint32_t off = b_lane + (uint32_t)np * (16 * RS) + (uint32_t)ks * 32u;
                ldsm4(bfh[np], bh + off);
                ldsm4(bfl[np], bl + off);
            }
#pragma unroll
            for (int mt = 0; mt < MT; mt++)
#pragma unroll
                for (int nt = 0; nt < 4; nt++) {
                    const uint32_t* Bh2 = &bfh[nt >> 1][(nt & 1) * 2];
                    const uint32_t* Bl2 = &bfl[nt >> 1][(nt & 1) * 2];
                    mma16816(acc[mt][nt], afh[mt], Bh2);
                    mma16816(acc[mt][nt], afh[mt], Bl2);
                    mma16816(acc[mt][nt], afl[mt], Bh2);
                }
        }
    };

    load_chunk(0, 0);
    for (int ck = 0; ck < NC; ck++) {
        if (ck + 1 < NC) { load_chunk(ck + 1, (ck + 1) & 1); cpwait1(); }
        else             { cpwait0(); }
        __syncthreads();
        compute(ck & 1);
        __syncthreads();
    }

#pragma unroll
    for (int mt = 0; mt < MT; mt++) {
#pragma unroll
        for (int nt = 0; nt < 4; nt++) {
            int r0 = row0 + wm0 + mt * 16 + (lane >> 2);
            int c0 = col0 + wn0 + nt * 8 + (lane & 3) * 2;
            float* a4 = acc[mt][nt];
            if (EPI == 0) {
#pragma unroll
                for (int h = 0; h < 2; h++) {
                    int gm = r0 + h * 8;
                    if (gm >= M) continue;
#pragma unroll
                    for (int q = 0; q < 2; q++) {
                        int gn = c0 + q;
                        if (gn >= N) continue;
                        float v = a4[h * 2 + q] * alpha;
                        if (bias) v += bias[gn];
                        if (res)  v += res[(size_t)gm * ldc + gn];
                        Cf[(size_t)gm * ldc + gn] = v;
                    }
                }
            } else {
#pragma unroll
                for (int h = 0; h < 2; h++) {
                    int gm = r0 + h * 8;
                    if (gm >= M) continue;
                    float v0 = a4[h * 2], v1 = a4[h * 2 + 1];
                    if (bias) { v0 += bias[c0]; v1 += bias[c0 + 1]; }
                    if (EPI == 2) { v0 = geluf(v0); v1 = geluf(v1); }
                    uint32_t lo, hi = packsplit_hi(v0, v1, lo);
                    *reinterpret_cast<uint32_t*>(Chi + (size_t)gm * ldc + c0) = hi;
                    *reinterpret_cast<uint32_t*>(Clo + (size_t)gm * ldc + c0) = lo;
                }
            }
        }
    }
}

// ---------------- host-side GEMM launcher ----------------
template <int BN, int EPI>
static void ggemm(const bf16* Ah, const bf16* Al, int lda,
                  const bf16* Bh, const bf16* Bl, int ldb,
                  float* Cf, bf16* Ch, bf16* Cl, int ldc,
                  const float* bias, const float* res,
                  int M, int N, int K, float alpha) {
    constexpr int RS = 144;
    constexpr int BUF = 2 * 128 * RS + 2 * BN * RS;
    int smem = 2 * BUF;
    cudaFuncSetAttribute(hmma_gemm<BN, EPI>, cudaFuncAttributeMaxDynamicSharedMemorySize, smem);
    dim3 grid((N + BN - 1) / BN, (M + 127) / 128, 1);
    hmma_gemm<BN, EPI><<<grid, 256, smem>>>(Ah, Al, lda, Bh, Bl, ldb, Cf, Ch, Cl, ldc,
                                            bias, res, M, N, K / 64, alpha);
}

extern "C" void kernel_launch(void* const* d_in, const int* in_sizes, int n_in,
                              void* d_out, int out_size) {
    const float* x       = (const float*)d_in[0];
    const float* conv_w  = (const float*)d_in[1];
    const float* conv_b  = (const float*)d_in[2];
    const float* cls_tok = (const float*)d_in[3];
    const float* pos_emb = (const float*)d_in[4];
    const float* ln1_g   = (const float*)d_in[5];
    const float* ln1_b   = (const float*)d_in[6];
    const float* qkv_w   = (const float*)d_in[7];
    const float* qkv_b   = (const float*)d_in[8];
    const float* proj_w  = (const float*)d_in[9];
    const float* proj_b  = (const float*)d_in[10];
    const float* ln2_g   = (const float*)d_in[11];
    const float* ln2_b   = (const float*)d_in[12];
    const float* mlp_w1  = (const float*)d_in[13];
    const float* mlp_b1  = (const float*)d_in[14];
    const float* mlp_w2  = (const float*)d_in[15];
    const float* mlp_b2  = (const float*)d_in[16];
    const float* lnf_g   = (const float*)d_in[17];
    const float* lnf_b   = (const float*)d_in[18];
    float* out = (float*)d_out;

    bf16 *phi, *plo, *cwhi, *cwlo, *whi, *wlo, *yhi, *ylo, *qhi, *qlo, *mhi, *mlo,
         *vthi, *vtlo;
    float *ph, *ptmp;
    cudaGetSymbolAddress((void**)&phi, g_phi);
    cudaGetSymbolAddress((void**)&plo, g_plo);
    cudaGetSymbolAddress((void**)&cwhi, g_cwhi);
    cudaGetSymbolAddress((void**)&cwlo, g_cwlo);
    cudaGetSymbolAddress((void**)&whi, g_whi);
    cudaGetSymbolAddress((void**)&wlo, g_wlo);
    cudaGetSymbolAddress((void**)&ph, g_h);
    cudaGetSymbolAddress((void**)&ptmp, g_ptmp);
    cudaGetSymbolAddress((void**)&yhi, g_yhi);
    cudaGetSymbolAddress((void**)&ylo, g_ylo);
    cudaGetSymbolAddress((void**)&qhi, g_qhi);
    cudaGetSymbolAddress((void**)&qlo, g_qlo);
    cudaGetSymbolAddress((void**)&mhi, g_mhi);
    cudaGetSymbolAddress((void**)&mlo, g_mlo);
    cudaGetSymbolAddress((void**)&vthi, g_vthi);
    cudaGetSymbolAddress((void**)&vtlo, g_vtlo);

    dim3 tb(32, 8);

    // ---- weight prep ----
    split_kernel<<<(DM * DM + 255) / 256, 256>>>(conv_w, cwhi, cwlo, DM * DM);
    for (int l = 0; l < LAYERS; l++) {
        long long wo = (long long)l * LW;
        wt_trans<<<dim3(2304 / 32, 768 / 32), tb>>>(qkv_w + (size_t)l * DM * 3 * DM,
                                                    whi + wo, wlo + wo, DM, 3 * DM);
        wt_trans<<<dim3(768 / 32, 768 / 32), tb>>>(proj_w + (size_t)l * DM * DM,
                                                   whi + wo + 1769472, wlo + wo + 1769472, DM, DM);
        wt_trans<<<dim3(3072 / 32, 768 / 32), tb>>>(mlp_w1 + (size_t)l * DM * 4 * DM,
                                                    whi + wo + 2359296, wlo + wo + 2359296, DM, 4 * DM);
        wt_trans<<<dim3(768 / 32, 3072 / 32), tb>>>(mlp_w2 + (size_t)l * 4 * DM * DM,
                                                    whi + wo + 4718592, wlo + wo + 4718592, 4 * DM, DM);
    }

    // ---- patch embed ----
    im2col_split<<<(MPATCH * DM + 255) / 256, 256>>>(x, phi, plo);
    ggemm<128, 0>(phi, plo, DM, cwhi, cwlo, DM, ptmp, nullptr, nullptr, DM,
                  conv_b, nullptr, MPATCH, DM, DM, 1.0f);
    assemble_kernel<<<(MTOK * DM + 255) / 256, 256>>>(ptmp, cls_tok, pos_emb, ph);

    cudaFuncSetAttribute(fused_attn, cudaFuncAttributeMaxDynamicSharedMemorySize, FA_SMEM);

    for (int l = 0; l < LAYERS; l++) {
        long long wo = (long long)l * LW;
        const bf16* qwT_h = whi + wo;            const bf16* qwT_l = wlo + wo;
        const bf16* pwT_h = whi + wo + 1769472;  const bf16* pwT_l = wlo + wo + 1769472;
        const bf16* w1T_h = whi + wo + 2359296;  const bf16* w1T_l = wlo + wo + 2359296;
        const bf16* w2T_h = whi + wo + 4718592;  const bf16* w2T_l = wlo + wo + 4718592;
        const float* l1g = ln1_g + (size_t)l * DM;
        const float* l1b = ln1_b + (size_t)l * DM;
        const float* qb  = qkv_b + (size_t)l * 3 * DM;
        const float* pb  = proj_b + (size_t)l * DM;
        const float* l2g = ln2_g + (size_t)l * DM;
        const float* l2b = ln2_b + (size_t)l * DM;
        const float* b1  = mlp_b1 + (size_t)l * 4 * DM;
        const float* b2  = mlp_b2 + (size_t)l * DM;

        // LN1 -> split y
        ln_split<<<MTOK, 256>>>(ph, l1g, l1b, yhi, ylo);
        // QKV
        ggemm<128, 1>(yhi, ylo, DM, qwT_h, qwT_l, DM, nullptr, qhi, qlo, 3 * DM,
                      qb, nullptr, MTOK, 3 * DM, DM, 1.0f);
        // V transpose per head (validated)
        {
            size_t n = (size_t)BATCH * HEADS * 64 * SPAD;
            vt_split<<<(unsigned)((n + 255) / 256), 256>>>(qhi, qlo, vthi, vtlo);
        }
        // fused attention -> y (split), [B,N,H,dh] == [B,N,D]
        fused_attn<<<dim3(NCHUNK, BATCH * HEADS), 256, FA_SMEM>>>(qhi, qlo, vthi, vtlo,
                                                                  yhi, ylo);
        // proj + bias + residual
        ggemm<128, 0>(yhi, ylo, DM, pwT_h, pwT_l, DM, ph, nullptr, nullptr, DM,
                      pb, ph, MTOK, DM, DM, 1.0f);
        // LN2 -> split y
        ln_split<<<MTOK, 256>>>(ph, l2g, l2b, yhi, ylo);
        // MLP1 + gelu
        ggemm<128, 2>(yhi, ylo, DM, w1T_h, w1T_l, DM, nullptr, mhi, mlo, 4 * DM,
                      b1, nullptr, MTOK, 4 * DM, DM, 1.0f);
        // MLP2 + bias + residual
        ggemm<128, 0>(mhi, mlo, 4 * DM, w2T_h, w2T_l, 4 * DM, ph, nullptr, nullptr, DM,
                      b2, ph, MTOK, DM, 4 * DM, 1.0f);
    }

    // final LN on CLS rows -> out [8,768]
    ln_kernel<<<BATCH, 256>>>(ph, lnf_g, lnf_b, out, (long long)NTOK * DM, DM);
}